// round 1
// baseline (speedup 1.0000x reference)
#include <cuda_runtime.h>
#include <cstdint>

#define EPSV 1e-9f

// Problem shapes (fixed for this dataset): B=16384, IN=2048, OUT=2048.
// Scratch lives in __device__ globals (no allocation allowed in kernel_launch).
#define MAX_B   16384
#define MAX_OUT 2048

__device__ float g_u[(size_t)MAX_B * MAX_OUT];  // relu(cosine) scratch, 128 MB
__device__ float g_invx[MAX_B];                  // 1/(||x_row||+eps)
__device__ float g_invw[MAX_OUT];                // 1/(||w_row||+eps)
__device__ float g_gmax;                         // global max of u (>=0)

// ---------------------------------------------------------------------------
// Kernel 1: per-row inverse norms for x (blocks [0,B)) and W (blocks [B,B+OUT)).
// Also resets g_gmax for this invocation (graph replay safe).
// ---------------------------------------------------------------------------
__global__ void __launch_bounds__(256)
norms_kernel(const float* __restrict__ x, const float* __restrict__ w,
             int B, int OUT, int IN)
{
    const int r = blockIdx.x;
    const float* src;
    float* dst;
    if (r < B) { src = x + (size_t)r * IN;        dst = &g_invx[r]; }
    else       { src = w + (size_t)(r - B) * IN;  dst = &g_invw[r - B]; }

    float s = 0.f;
    const float4* p = reinterpret_cast<const float4*>(src);
    const int n4 = IN >> 2;
    for (int i = threadIdx.x; i < n4; i += blockDim.x) {
        float4 v = p[i];
        s += v.x * v.x + v.y * v.y + v.z * v.z + v.w * v.w;
    }

    // block reduce (sum)
    #pragma unroll
    for (int o = 16; o; o >>= 1) s += __shfl_xor_sync(0xffffffffu, s, o);
    __shared__ float red[8];
    const int lane = threadIdx.x & 31, wid = threadIdx.x >> 5;
    if (lane == 0) red[wid] = s;
    __syncthreads();
    if (threadIdx.x == 0) {
        float t = 0.f;
        const int nw = blockDim.x >> 5;
        for (int i = 0; i < nw; ++i) t += red[i];
        *dst = 1.f / (sqrtf(t) + EPSV);
        if (r == 0) g_gmax = 0.f;
    }
}

// ---------------------------------------------------------------------------
// Kernel 2: a = x @ W^T with fused cosine scaling + ReLU + global-max tracking.
// Classic 128x128x8 SIMT SGEMM, 256 threads, 8x8 microtile.
// Both operands are K-contiguous (NT gemm), loaded as float4, stored transposed
// into SMEM [BK][BM].
// ---------------------------------------------------------------------------
__global__ void __launch_bounds__(256)
softhebb_gemm_kernel(const float* __restrict__ X, const float* __restrict__ W,
                     int M, int N, int K)
{
    __shared__ float As[8][128];
    __shared__ float Bs[8][128];

    const int tid = threadIdx.x;
    const int lr  = tid >> 1;         // 0..127: tile row to load
    const int lk  = (tid & 1) << 2;   // 0 or 4: k offset of the float4
    const int tx  = tid & 15;         // microtile col group
    const int ty  = tid >> 4;         // microtile row group

    const int row0 = blockIdx.y * 128;
    const int col0 = blockIdx.x * 128;

    const float* Xp = X + (size_t)(row0 + lr) * K + lk;
    const float* Wp = W + (size_t)(col0 + lr) * K + lk;

    float acc[8][8];
    #pragma unroll
    for (int i = 0; i < 8; ++i)
        #pragma unroll
        for (int j = 0; j < 8; ++j) acc[i][j] = 0.f;

    for (int k0 = 0; k0 < K; k0 += 8) {
        const float4 av = *reinterpret_cast<const float4*>(Xp + k0);
        const float4 bv = *reinterpret_cast<const float4*>(Wp + k0);
        __syncthreads();
        As[lk + 0][lr] = av.x; As[lk + 1][lr] = av.y;
        As[lk + 2][lr] = av.z; As[lk + 3][lr] = av.w;
        Bs[lk + 0][lr] = bv.x; Bs[lk + 1][lr] = bv.y;
        Bs[lk + 2][lr] = bv.z; Bs[lk + 3][lr] = bv.w;
        __syncthreads();

        #pragma unroll
        for (int kk = 0; kk < 8; ++kk) {
            float4 a0 = *reinterpret_cast<const float4*>(&As[kk][ty * 8]);
            float4 a1 = *reinterpret_cast<const float4*>(&As[kk][ty * 8 + 4]);
            float4 b0 = *reinterpret_cast<const float4*>(&Bs[kk][tx * 8]);
            float4 b1 = *reinterpret_cast<const float4*>(&Bs[kk][tx * 8 + 4]);
            float a[8] = {a0.x, a0.y, a0.z, a0.w, a1.x, a1.y, a1.z, a1.w};
            float b[8] = {b0.x, b0.y, b0.z, b0.w, b1.x, b1.y, b1.z, b1.w};
            #pragma unroll
            for (int i = 0; i < 8; ++i)
                #pragma unroll
                for (int j = 0; j < 8; ++j)
                    acc[i][j] = fmaf(a[i], b[j], acc[i][j]);
        }
    }

    // Epilogue: cosine scale + ReLU + store u + track max
    float sr[8], sc[8];
    #pragma unroll
    for (int i = 0; i < 8; ++i) sr[i] = g_invx[row0 + ty * 8 + i];
    #pragma unroll
    for (int j = 0; j < 8; ++j) sc[j] = g_invw[col0 + tx * 8 + j];

    float tmax = 0.f;
    #pragma unroll
    for (int i = 0; i < 8; ++i) {
        float tmp[8];
        #pragma unroll
        for (int j = 0; j < 8; ++j) {
            float v = fmaxf(acc[i][j] * sr[i] * sc[j], 0.f);
            tmp[j] = v;
            tmax = fmaxf(tmax, v);
        }
        const size_t off = (size_t)(row0 + ty * 8 + i) * N + (col0 + tx * 8);
        *reinterpret_cast<float4*>(&g_u[off])     = make_float4(tmp[0], tmp[1], tmp[2], tmp[3]);
        *reinterpret_cast<float4*>(&g_u[off + 4]) = make_float4(tmp[4], tmp[5], tmp[6], tmp[7]);
    }

    // block max reduce -> one atomic per block (float>=0, int ordering matches)
    #pragma unroll
    for (int o = 16; o; o >>= 1) tmax = fmaxf(tmax, __shfl_xor_sync(0xffffffffu, tmax, o));
    __shared__ float wmax[8];
    if ((tid & 31) == 0) wmax[tid >> 5] = tmax;
    __syncthreads();
    if (tid == 0) {
        float m = wmax[0];
        #pragma unroll
        for (int i = 1; i < 8; ++i) m = fmaxf(m, wmax[i]);
        atomicMax(reinterpret_cast<int*>(&g_gmax), __float_as_int(m));
    }
}

// ---------------------------------------------------------------------------
// Kernel 3: per-row power-law + logprior + row-sum normalize.
// One block per row; row buffered in SMEM.
// ---------------------------------------------------------------------------
__global__ void __launch_bounds__(256)
finalize_kernel(const float* __restrict__ logprior, const float* __restrict__ lamb_p,
                float* __restrict__ y, int N)
{
    const int r = blockIdx.x;
    const float lamb = lamb_p[0];
    const float inv_umax = 1.f / (g_gmax + EPSV);

    __shared__ float buf[MAX_OUT];
    const float4* u4  = reinterpret_cast<const float4*>(&g_u[(size_t)r * N]);
    const float4* lp4 = reinterpret_cast<const float4*>(logprior);
    float4* b4        = reinterpret_cast<float4*>(buf);

    const int n4 = N >> 2;
    float s = 0.f;
    for (int i = threadIdx.x; i < n4; i += blockDim.x) {
        float4 u = u4[i];
        float4 lp = lp4[i];
        float4 p;
        p.x = (u.x > 0.f) ? exp2f(lamb * log2f(u.x * inv_umax)) * expf(lp.x) : 0.f;
        p.y = (u.y > 0.f) ? exp2f(lamb * log2f(u.y * inv_umax)) * expf(lp.y) : 0.f;
        p.z = (u.z > 0.f) ? exp2f(lamb * log2f(u.z * inv_umax)) * expf(lp.z) : 0.f;
        p.w = (u.w > 0.f) ? exp2f(lamb * log2f(u.w * inv_umax)) * expf(lp.w) : 0.f;
        b4[i] = p;
        s += p.x + p.y + p.z + p.w;
    }

    // block reduce (sum)
    #pragma unroll
    for (int o = 16; o; o >>= 1) s += __shfl_xor_sync(0xffffffffu, s, o);
    __shared__ float red[8];
    __shared__ float inv_sum_sh;
    const int lane = threadIdx.x & 31, wid = threadIdx.x >> 5;
    if (lane == 0) red[wid] = s;
    __syncthreads();
    if (threadIdx.x == 0) {
        float t = 0.f;
        const int nw = blockDim.x >> 5;
        for (int i = 0; i < nw; ++i) t += red[i];
        inv_sum_sh = 1.f / (t + EPSV);
    }
    __syncthreads();
    const float inv_sum = inv_sum_sh;

    float4* y4 = reinterpret_cast<float4*>(y + (size_t)r * N);
    for (int i = threadIdx.x; i < n4; i += blockDim.x) {
        float4 p = b4[i];
        p.x *= inv_sum; p.y *= inv_sum; p.z *= inv_sum; p.w *= inv_sum;
        y4[i] = p;
    }
}

// ---------------------------------------------------------------------------
// Launcher. Inputs (metadata order): x [B,IN] f32, weight [OUT,IN] f32,
// logprior [OUT] f32, lamb [1] f32. Output: y [B,OUT] f32.
// ---------------------------------------------------------------------------
extern "C" void kernel_launch(void* const* d_in, const int* in_sizes, int n_in,
                              void* d_out, int out_size)
{
    const float* x        = (const float*)d_in[0];
    const float* w        = (const float*)d_in[1];
    const float* logprior = (const float*)d_in[2];
    const float* lamb     = (const float*)d_in[3];
    float* y              = (float*)d_out;

    const int OUT = in_sizes[2];
    const int IN  = in_sizes[1] / OUT;
    const int B   = in_sizes[0] / IN;

    norms_kernel<<<B + OUT, 256>>>(x, w, B, OUT, IN);

    dim3 grid(OUT / 128, B / 128);
    softhebb_gemm_kernel<<<grid, 256>>>(x, w, B, OUT, IN);

    finalize_kernel<<<B, 256>>>(logprior, lamb, y, OUT);
}

// round 3
// speedup vs baseline: 2.2731x; 2.2731x over previous
#include <cuda_runtime.h>
#include <cuda_bf16.h>
#include <cstdint>

#define EPSV 1e-9f

// Fixed problem shape: B=16384, IN=K=2048, OUT=2048
#define B_DIM   16384
#define K_DIM   2048
#define O_DIM   2048

// ---------------------------------------------------------------------------
// Device scratch (no allocations allowed in kernel_launch)
// ---------------------------------------------------------------------------
__device__ float g_u[(size_t)B_DIM * O_DIM];      // relu(cos) scratch (128 MB)
__device__ float g_invx[B_DIM];
__device__ float g_invw[O_DIM];
__device__ float g_gmax;
__device__ __align__(16) __nv_bfloat16 g_xhi[(size_t)B_DIM * K_DIM];
__device__ __align__(16) __nv_bfloat16 g_xlo[(size_t)B_DIM * K_DIM];
__device__ __align__(16) __nv_bfloat16 g_whi[(size_t)O_DIM * K_DIM];
__device__ __align__(16) __nv_bfloat16 g_wlo[(size_t)O_DIM * K_DIM];

// ---------------------------------------------------------------------------
// PTX helpers (family-safe only: ldmatrix, mma.sync, cp.async)
// ---------------------------------------------------------------------------
__device__ __forceinline__ uint32_t smem_u32(const void* p) {
    uint32_t a;
    asm("{ .reg .u64 t; cvta.to.shared.u64 t, %1; cvt.u32.u64 %0, t; }"
        : "=r"(a) : "l"(p));
    return a;
}

#define CP16(saddr, gptr) \
    asm volatile("cp.async.cg.shared.global [%0], [%1], 16;" \
                 :: "r"(saddr), "l"(gptr) : "memory")
#define CP_COMMIT() asm volatile("cp.async.commit_group;" ::: "memory")
#define CP_WAIT1()  asm volatile("cp.async.wait_group 1;" ::: "memory")
#define CP_WAIT0()  asm volatile("cp.async.wait_group 0;" ::: "memory")

#define LDSM_X4(r0, r1, r2, r3, addr) \
    asm volatile("ldmatrix.sync.aligned.m8n8.x4.shared.b16 {%0,%1,%2,%3}, [%4];" \
                 : "=r"(r0), "=r"(r1), "=r"(r2), "=r"(r3) : "r"(addr))

#define MMA_BF16(d, a, b) \
    asm volatile("mma.sync.aligned.m16n8k16.row.col.f32.bf16.bf16.f32 " \
                 "{%0,%1,%2,%3}, {%4,%5,%6,%7}, {%8,%9}, {%0,%1,%2,%3};" \
                 : "+f"((d)[0]), "+f"((d)[1]), "+f"((d)[2]), "+f"((d)[3]) \
                 : "r"((a)[0]), "r"((a)[1]), "r"((a)[2]), "r"((a)[3]),   \
                   "r"((b)[0]), "r"((b)[1]))

// ---------------------------------------------------------------------------
// Kernel 1: fused per-row inv-norms + bf16 hi/lo split for x and W.
// ---------------------------------------------------------------------------
__global__ void __launch_bounds__(256)
prep_kernel(const float* __restrict__ x, const float* __restrict__ w,
            int B, int OUT, int IN)
{
    const int r = blockIdx.x;
    const float* src;
    __nv_bfloat16 *hi, *lo;
    float* dst;
    if (r < B) {
        src = x + (size_t)r * IN;
        hi = g_xhi + (size_t)r * IN; lo = g_xlo + (size_t)r * IN;
        dst = &g_invx[r];
    } else {
        const int rr = r - B;
        src = w + (size_t)rr * IN;
        hi = g_whi + (size_t)rr * IN; lo = g_wlo + (size_t)rr * IN;
        dst = &g_invw[rr];
    }

    float s = 0.f;
    const float4* p4 = reinterpret_cast<const float4*>(src);
    uint2* h2 = reinterpret_cast<uint2*>(hi);
    uint2* l2 = reinterpret_cast<uint2*>(lo);
    const int n4 = IN >> 2;
    for (int i = threadIdx.x; i < n4; i += blockDim.x) {
        float4 v = p4[i];
        s += v.x * v.x + v.y * v.y + v.z * v.z + v.w * v.w;
        __nv_bfloat16 ha = __float2bfloat16_rn(v.x);
        __nv_bfloat16 hb = __float2bfloat16_rn(v.y);
        __nv_bfloat16 hc = __float2bfloat16_rn(v.z);
        __nv_bfloat16 hd = __float2bfloat16_rn(v.w);
        __nv_bfloat16 la = __float2bfloat16_rn(v.x - __bfloat162float(ha));
        __nv_bfloat16 lb = __float2bfloat16_rn(v.y - __bfloat162float(hb));
        __nv_bfloat16 lc = __float2bfloat16_rn(v.z - __bfloat162float(hc));
        __nv_bfloat16 ld = __float2bfloat16_rn(v.w - __bfloat162float(hd));
        uint2 uh, ul;
        uh.x = (uint32_t)__bfloat16_as_ushort(ha) | ((uint32_t)__bfloat16_as_ushort(hb) << 16);
        uh.y = (uint32_t)__bfloat16_as_ushort(hc) | ((uint32_t)__bfloat16_as_ushort(hd) << 16);
        ul.x = (uint32_t)__bfloat16_as_ushort(la) | ((uint32_t)__bfloat16_as_ushort(lb) << 16);
        ul.y = (uint32_t)__bfloat16_as_ushort(lc) | ((uint32_t)__bfloat16_as_ushort(ld) << 16);
        h2[i] = uh;
        l2[i] = ul;
    }

    #pragma unroll
    for (int o = 16; o; o >>= 1) s += __shfl_xor_sync(0xffffffffu, s, o);
    __shared__ float red[8];
    const int lane = threadIdx.x & 31, wid = threadIdx.x >> 5;
    if (lane == 0) red[wid] = s;
    __syncthreads();
    if (threadIdx.x == 0) {
        float t = 0.f;
        for (int i = 0; i < 8; ++i) t += red[i];
        *dst = 1.f / (sqrtf(t) + EPSV);
        if (r == 0) g_gmax = 0.f;
    }
}

// ---------------------------------------------------------------------------
// Kernel 2: mma.sync bf16 3-term split GEMM + fused cosine/ReLU/max epilogue.
// CTA 128x128, 8 warps (4 M x 2 N), warp tile 32x64.
// K chunks of 32, cp.async double buffer.
// SMEM per stage: Ahi/Alo/Bhi/Blo, each 128 rows x 80B (64B data + 16B pad).
// 80B row stride => conflict-free ldmatrix (16B-chunk idx pattern 0,5,2,7,4,1,6,3).
// ---------------------------------------------------------------------------
#define ROWB     80
#define T_AHI    0
#define T_ALO    10240
#define T_BHI    20480
#define T_BLO    30720
#define STAGE_SZ 40960
#define DYN_SMEM (2 * STAGE_SZ)

__global__ void __launch_bounds__(256, 1)
softhebb_mma_gemm(int M, int N, int K)
{
    extern __shared__ char sm[];
    const uint32_t sbase = smem_u32(sm);

    const int tid  = threadIdx.x;
    const int wid  = tid >> 5;
    const int lane = tid & 31;
    const int wm   = wid & 3;   // M warp (0..3): rows wm*32..+31
    const int wn   = wid >> 2;  // N warp (0..1): cols wn*64..+63

    const int row0 = blockIdx.y * 128;
    const int col0 = blockIdx.x * 128;

    float acc[2][8][4];
    #pragma unroll
    for (int i = 0; i < 2; ++i)
        #pragma unroll
        for (int j = 0; j < 8; ++j)
            #pragma unroll
            for (int q = 0; q < 4; ++q) acc[i][j][q] = 0.f;

    const int nchunks = K >> 5;  // 64

    // ldmatrix base addresses (stage 0; add stage offset per iter)
    // A: lanes 0-15 -> rows 0-15 (k 0-7), lanes 16-31 -> rows 0-15 (k 8-15)
    const uint32_t a_lm = (uint32_t)((wm * 32 + (lane & 15)) * ROWB + (lane >> 4) * 16);
    // B: lanes 0-7 n0-7/k0, 8-15 n0-7/k8, 16-23 n8-15/k0, 24-31 n8-15/k8
    const uint32_t b_lm = (uint32_t)((wn * 64 + (lane & 7) + ((lane >> 4) << 3)) * ROWB
                                     + (((lane >> 3) & 1) << 4));

    // cp.async chunk mapping: 512 x 16B chunks per tile; thread does {tid, tid+256}
    #define LOAD_STAGE(chunk, stg) do {                                          \
        const int kel = (chunk) << 5;                                            \
        const uint32_t sb = sbase + (stg) * STAGE_SZ;                            \
        _Pragma("unroll")                                                        \
        for (int t = 0; t < 2; ++t) {                                            \
            const int c = tid + (t << 8);                                        \
            const int r = c >> 2, q = c & 3;                                     \
            const uint32_t so = (uint32_t)(r * ROWB + q * 16);                   \
            const size_t ga = (size_t)(row0 + r) * K + kel + q * 8;              \
            const size_t gb = (size_t)(col0 + r) * K + kel + q * 8;              \
            CP16(sb + T_AHI + so, g_xhi + ga);                                   \
            CP16(sb + T_ALO + so, g_xlo + ga);                                   \
            CP16(sb + T_BHI + so, g_whi + gb);                                   \
            CP16(sb + T_BLO + so, g_wlo + gb);                                   \
        }                                                                        \
    } while (0)

    LOAD_STAGE(0, 0);
    CP_COMMIT();

    for (int c = 0; c < nchunks; ++c) {
        if (c + 1 < nchunks) {
            LOAD_STAGE(c + 1, (c + 1) & 1);
            CP_COMMIT();
            CP_WAIT1();
        } else {
            CP_WAIT0();
        }
        __syncthreads();

        const uint32_t sb = sbase + (c & 1) * STAGE_SZ;
        #pragma unroll
        for (int kk = 0; kk < 2; ++kk) {
            const uint32_t ko = kk << 5;  // 32B per k16 step
            uint32_t ah[2][4], al[2][4];
            #pragma unroll
            for (int mf = 0; mf < 2; ++mf) {
                const uint32_t ao = a_lm + mf * (16 * ROWB) + ko;
                LDSM_X4(ah[mf][0], ah[mf][1], ah[mf][2], ah[mf][3], sb + T_AHI + ao);
                LDSM_X4(al[mf][0], al[mf][1], al[mf][2], al[mf][3], sb + T_ALO + ao);
            }
            uint32_t bh[4][4], bl[4][4];
            #pragma unroll
            for (int np = 0; np < 4; ++np) {
                const uint32_t bo = b_lm + np * (16 * ROWB) + ko;
                LDSM_X4(bh[np][0], bh[np][1], bh[np][2], bh[np][3], sb + T_BHI + bo);
                LDSM_X4(bl[np][0], bl[np][1], bl[np][2], bl[np][3], sb + T_BLO + bo);
            }
            #pragma unroll
            for (int mf = 0; mf < 2; ++mf) {
                #pragma unroll
                for (int np = 0; np < 4; ++np) {
                    // b-frag for n-subtile 0: regs {0,1}; subtile 1: regs {2,3}
                    MMA_BF16(acc[mf][2 * np],     ah[mf], (&bh[np][0]));
                    MMA_BF16(acc[mf][2 * np],     ah[mf], (&bl[np][0]));
                    MMA_BF16(acc[mf][2 * np],     al[mf], (&bh[np][0]));
                    MMA_BF16(acc[mf][2 * np + 1], ah[mf], (&bh[np][2]));
                    MMA_BF16(acc[mf][2 * np + 1], ah[mf], (&bl[np][2]));
                    MMA_BF16(acc[mf][2 * np + 1], al[mf], (&bh[np][2]));
                }
            }
        }
        __syncthreads();
    }

    // Epilogue: cosine scale + ReLU + store u + global max
    const int g  = lane >> 2;   // group id 0..7
    const int tg = lane & 3;
    float tmax = 0.f;
    #pragma unroll
    for (int mf = 0; mf < 2; ++mf) {
        const int ra = row0 + wm * 32 + mf * 16 + g;
        const float s0 = g_invx[ra];
        const float s1 = g_invx[ra + 8];
        #pragma unroll
        for (int nf = 0; nf < 8; ++nf) {
            const int col = col0 + wn * 64 + nf * 8 + tg * 2;
            const float w0 = g_invw[col];
            const float w1 = g_invw[col + 1];
            float2 v0, v1;
            v0.x = fmaxf(acc[mf][nf][0] * s0 * w0, 0.f);
            v0.y = fmaxf(acc[mf][nf][1] * s0 * w1, 0.f);
            v1.x = fmaxf(acc[mf][nf][2] * s1 * w0, 0.f);
            v1.y = fmaxf(acc[mf][nf][3] * s1 * w1, 0.f);
            tmax = fmaxf(tmax, fmaxf(fmaxf(v0.x, v0.y), fmaxf(v1.x, v1.y)));
            *reinterpret_cast<float2*>(&g_u[(size_t)ra * N + col])       = v0;
            *reinterpret_cast<float2*>(&g_u[(size_t)(ra + 8) * N + col]) = v1;
        }
    }

    #pragma unroll
    for (int o = 16; o; o >>= 1)
        tmax = fmaxf(tmax, __shfl_xor_sync(0xffffffffu, tmax, o));
    __shared__ float wmax[8];
    if (lane == 0) wmax[wid] = tmax;
    __syncthreads();
    if (tid == 0) {
        float m = wmax[0];
        #pragma unroll
        for (int i = 1; i < 8; ++i) m = fmaxf(m, wmax[i]);
        atomicMax(reinterpret_cast<int*>(&g_gmax), __float_as_int(m));
    }
}

// ---------------------------------------------------------------------------
// Kernel 3: per-row power-law + logprior + row-sum normalize.
// ---------------------------------------------------------------------------
__global__ void __launch_bounds__(256)
finalize_kernel(const float* __restrict__ logprior, const float* __restrict__ lamb_p,
                float* __restrict__ y, int N)
{
    const int r = blockIdx.x;
    const float lamb = lamb_p[0];
    const float inv_umax = 1.f / (g_gmax + EPSV);

    __shared__ float buf[O_DIM];
    const float4* u4  = reinterpret_cast<const float4*>(&g_u[(size_t)r * N]);
    const float4* lp4 = reinterpret_cast<const float4*>(logprior);
    float4* b4        = reinterpret_cast<float4*>(buf);

    const int n4 = N >> 2;
    float s = 0.f;
    for (int i = threadIdx.x; i < n4; i += blockDim.x) {
        float4 u = u4[i];
        float4 lp = lp4[i];
        float4 p;
        p.x = (u.x > 0.f) ? exp2f(lamb * log2f(u.x * inv_umax)) * expf(lp.x) : 0.f;
        p.y = (u.y > 0.f) ? exp2f(lamb * log2f(u.y * inv_umax)) * expf(lp.y) : 0.f;
        p.z = (u.z > 0.f) ? exp2f(lamb * log2f(u.z * inv_umax)) * expf(lp.z) : 0.f;
        p.w = (u.w > 0.f) ? exp2f(lamb * log2f(u.w * inv_umax)) * expf(lp.w) : 0.f;
        b4[i] = p;
        s += p.x + p.y + p.z + p.w;
    }

    #pragma unroll
    for (int o = 16; o; o >>= 1) s += __shfl_xor_sync(0xffffffffu, s, o);
    __shared__ float red[8];
    __shared__ float inv_sum_sh;
    const int lane = threadIdx.x & 31, wid = threadIdx.x >> 5;
    if (lane == 0) red[wid] = s;
    __syncthreads();
    if (threadIdx.x == 0) {
        float t = 0.f;
        for (int i = 0; i < 8; ++i) t += red[i];
        inv_sum_sh = 1.f / (t + EPSV);
    }
    __syncthreads();
    const float inv_sum = inv_sum_sh;

    float4* y4 = reinterpret_cast<float4*>(y + (size_t)r * N);
    for (int i = threadIdx.x; i < n4; i += blockDim.x) {
        float4 p = b4[i];
        p.x *= inv_sum; p.y *= inv_sum; p.z *= inv_sum; p.w *= inv_sum;
        y4[i] = p;
    }
}

// ---------------------------------------------------------------------------
// Launcher. Inputs: x [B,IN] f32, weight [OUT,IN] f32, logprior [OUT] f32,
// lamb [1] f32. Output: y [B,OUT] f32.
// ---------------------------------------------------------------------------
extern "C" void kernel_launch(void* const* d_in, const int* in_sizes, int n_in,
                              void* d_out, int out_size)
{
    const float* x        = (const float*)d_in[0];
    const float* w        = (const float*)d_in[1];
    const float* logprior = (const float*)d_in[2];
    const float* lamb     = (const float*)d_in[3];
    float* y              = (float*)d_out;

    const int OUT = in_sizes[2];
    const int IN  = in_sizes[1] / OUT;
    const int B   = in_sizes[0] / IN;

    cudaFuncSetAttribute(softhebb_mma_gemm,
                         cudaFuncAttributeMaxDynamicSharedMemorySize, DYN_SMEM);

    prep_kernel<<<B + OUT, 256>>>(x, w, B, OUT, IN);

    dim3 grid(OUT / 128, B / 128);
    softhebb_mma_gemm<<<grid, 256, DYN_SMEM>>>(B, OUT, IN);

    finalize_kernel<<<B, 256>>>(logprior, lamb, y, OUT);
}

// round 4
// speedup vs baseline: 2.6674x; 1.1735x over previous
#include <cuda_runtime.h>
#include <cuda_bf16.h>
#include <cstdint>

#define EPSV 1e-9f

// Fixed problem shape: B=16384, IN=K=2048, OUT=2048
#define B_DIM   16384
#define K_DIM   2048
#define O_DIM   2048

// ---------------------------------------------------------------------------
// Device scratch (no allocations allowed in kernel_launch)
// ---------------------------------------------------------------------------
__device__ float g_u[(size_t)B_DIM * O_DIM];      // relu(cos) scratch (128 MB)
__device__ float g_invx[B_DIM];
__device__ float g_invw[O_DIM];
__device__ float g_gmax;
__device__ __align__(16) __nv_bfloat16 g_xhi[(size_t)B_DIM * K_DIM];
__device__ __align__(16) __nv_bfloat16 g_xlo[(size_t)B_DIM * K_DIM];
__device__ __align__(16) __nv_bfloat16 g_whi[(size_t)O_DIM * K_DIM];
__device__ __align__(16) __nv_bfloat16 g_wlo[(size_t)O_DIM * K_DIM];

// ---------------------------------------------------------------------------
// PTX helpers (family-safe: ldmatrix, mma.sync, cp.async)
// ---------------------------------------------------------------------------
__device__ __forceinline__ uint32_t smem_u32(const void* p) {
    uint32_t a;
    asm("{ .reg .u64 t; cvta.to.shared.u64 t, %1; cvt.u32.u64 %0, t; }"
        : "=r"(a) : "l"(p));
    return a;
}

#define CP16(saddr, gptr) \
    asm volatile("cp.async.cg.shared.global [%0], [%1], 16;" \
                 :: "r"(saddr), "l"(gptr) : "memory")
#define CP_COMMIT() asm volatile("cp.async.commit_group;" ::: "memory")
#define CP_WAIT1()  asm volatile("cp.async.wait_group 1;" ::: "memory")

#define LDSM_X4(r0, r1, r2, r3, addr) \
    asm volatile("ldmatrix.sync.aligned.m8n8.x4.shared.b16 {%0,%1,%2,%3}, [%4];" \
                 : "=r"(r0), "=r"(r1), "=r"(r2), "=r"(r3) : "r"(addr))

#define MMA_BF16(d, a, b) \
    asm volatile("mma.sync.aligned.m16n8k16.row.col.f32.bf16.bf16.f32 " \
                 "{%0,%1,%2,%3}, {%4,%5,%6,%7}, {%8,%9}, {%0,%1,%2,%3};" \
                 : "+f"((d)[0]), "+f"((d)[1]), "+f"((d)[2]), "+f"((d)[3]) \
                 : "r"((a)[0]), "r"((a)[1]), "r"((a)[2]), "r"((a)[3]),   \
                   "r"((b)[0]), "r"((b)[1]))

// ---------------------------------------------------------------------------
// Kernel 1: fused per-row inv-norms + bf16 hi/lo split for x and W.
// ---------------------------------------------------------------------------
__global__ void __launch_bounds__(256)
prep_kernel(const float* __restrict__ x, const float* __restrict__ w,
            int B, int OUT, int IN)
{
    const int r = blockIdx.x;
    const float* src;
    __nv_bfloat16 *hi, *lo;
    float* dst;
    if (r < B) {
        src = x + (size_t)r * IN;
        hi = g_xhi + (size_t)r * IN; lo = g_xlo + (size_t)r * IN;
        dst = &g_invx[r];
    } else {
        const int rr = r - B;
        src = w + (size_t)rr * IN;
        hi = g_whi + (size_t)rr * IN; lo = g_wlo + (size_t)rr * IN;
        dst = &g_invw[rr];
    }

    float s = 0.f;
    const float4* p4 = reinterpret_cast<const float4*>(src);
    uint2* h2 = reinterpret_cast<uint2*>(hi);
    uint2* l2 = reinterpret_cast<uint2*>(lo);
    const int n4 = IN >> 2;
    for (int i = threadIdx.x; i < n4; i += blockDim.x) {
        float4 v = p4[i];
        s += v.x * v.x + v.y * v.y + v.z * v.z + v.w * v.w;
        __nv_bfloat16 ha = __float2bfloat16_rn(v.x);
        __nv_bfloat16 hb = __float2bfloat16_rn(v.y);
        __nv_bfloat16 hc = __float2bfloat16_rn(v.z);
        __nv_bfloat16 hd = __float2bfloat16_rn(v.w);
        __nv_bfloat16 la = __float2bfloat16_rn(v.x - __bfloat162float(ha));
        __nv_bfloat16 lb = __float2bfloat16_rn(v.y - __bfloat162float(hb));
        __nv_bfloat16 lc = __float2bfloat16_rn(v.z - __bfloat162float(hc));
        __nv_bfloat16 ld = __float2bfloat16_rn(v.w - __bfloat162float(hd));
        uint2 uh, ul;
        uh.x = (uint32_t)__bfloat16_as_ushort(ha) | ((uint32_t)__bfloat16_as_ushort(hb) << 16);
        uh.y = (uint32_t)__bfloat16_as_ushort(hc) | ((uint32_t)__bfloat16_as_ushort(hd) << 16);
        ul.x = (uint32_t)__bfloat16_as_ushort(la) | ((uint32_t)__bfloat16_as_ushort(lb) << 16);
        ul.y = (uint32_t)__bfloat16_as_ushort(lc) | ((uint32_t)__bfloat16_as_ushort(ld) << 16);
        h2[i] = uh;
        l2[i] = ul;
    }

    #pragma unroll
    for (int o = 16; o; o >>= 1) s += __shfl_xor_sync(0xffffffffu, s, o);
    __shared__ float red[8];
    const int lane = threadIdx.x & 31, wid = threadIdx.x >> 5;
    if (lane == 0) red[wid] = s;
    __syncthreads();
    if (threadIdx.x == 0) {
        float t = 0.f;
        for (int i = 0; i < 8; ++i) t += red[i];
        *dst = 1.f / (sqrtf(t) + EPSV);
        if (r == 0) g_gmax = 0.f;
    }
}

// ---------------------------------------------------------------------------
// Kernel 2: mma.sync bf16 3-term split GEMM + fused cosine/ReLU/max epilogue.
// CTA 128x256, 512 threads, 16 warps (4 M x 4 N), warp tile 32x64.
// K chunks of 32, cp.async 3-stage pipeline, one __syncthreads per chunk.
// SMEM per stage: Ahi/Alo 128x80B, Bhi/Blo 256x80B (64B data + 16B pad).
// 80B row stride => conflict-free ldmatrix.
// ---------------------------------------------------------------------------
#define ROWB     80
#define T_AHI    0
#define T_ALO    10240
#define T_BHI    20480
#define T_BLO    40960
#define STAGE_SZ 61440
#define NSTAGE   3
#define DYN_SMEM (NSTAGE * STAGE_SZ)

__global__ void __launch_bounds__(512, 1)
softhebb_mma_gemm(int M, int N, int K)
{
    extern __shared__ char sm[];
    const uint32_t sbase = smem_u32(sm);

    const int tid  = threadIdx.x;
    const int wid  = tid >> 5;
    const int lane = tid & 31;
    const int wm   = wid & 3;   // M warp (0..3): rows wm*32..+31
    const int wn   = wid >> 2;  // N warp (0..3): cols wn*64..+63

    const int row0 = blockIdx.y * 128;
    const int col0 = blockIdx.x * 256;

    float acc[2][8][4];
    #pragma unroll
    for (int i = 0; i < 2; ++i)
        #pragma unroll
        for (int j = 0; j < 8; ++j)
            #pragma unroll
            for (int q = 0; q < 4; ++q) acc[i][j][q] = 0.f;

    const int nchunks = K >> 5;  // 64

    // ldmatrix base addresses (within a stage)
    const uint32_t a_lm = (uint32_t)((wm * 32 + (lane & 15)) * ROWB + (lane >> 4) * 16);
    const uint32_t b_lm = (uint32_t)((wn * 64 + (lane & 7) + ((lane >> 4) << 3)) * ROWB
                                     + (((lane >> 3) & 1) << 4));

    // Per-stage load: A 512 x 16B chunks (thread -> 1), B 1024 chunks (thread -> 2)
    #define LOAD_STAGE(chunk, stg) do {                                          \
        const int kel = (chunk) << 5;                                            \
        const uint32_t sb_ = sbase + (stg) * STAGE_SZ;                           \
        {                                                                        \
            const int r = tid >> 2, q = tid & 3;                                 \
            const uint32_t so = (uint32_t)(r * ROWB + q * 16);                   \
            const size_t ga = (size_t)(row0 + r) * K + kel + q * 8;              \
            CP16(sb_ + T_AHI + so, g_xhi + ga);                                  \
            CP16(sb_ + T_ALO + so, g_xlo + ga);                                  \
        }                                                                        \
        _Pragma("unroll")                                                        \
        for (int t = 0; t < 2; ++t) {                                            \
            const int c_ = tid + (t << 9);                                       \
            const int r = c_ >> 2, q = c_ & 3;                                   \
            const uint32_t so = (uint32_t)(r * ROWB + q * 16);                   \
            const size_t gb = (size_t)(col0 + r) * K + kel + q * 8;              \
            CP16(sb_ + T_BHI + so, g_whi + gb);                                  \
            CP16(sb_ + T_BLO + so, g_wlo + gb);                                  \
        }                                                                        \
    } while (0)

    LOAD_STAGE(0, 0);
    CP_COMMIT();
    LOAD_STAGE(1, 1);
    CP_COMMIT();

    int cbuf = 0, lbuf = 2;
    for (int c = 0; c < nchunks; ++c) {
        CP_WAIT1();          // chunk c resident
        __syncthreads();     // all warps past compute(c-1); safe to overwrite lbuf

        if (c + 2 < nchunks) LOAD_STAGE(c + 2, lbuf);
        CP_COMMIT();         // commit every iter to keep group accounting uniform

        const uint32_t sb = sbase + cbuf * STAGE_SZ;
        #pragma unroll
        for (int kk = 0; kk < 2; ++kk) {
            const uint32_t ko = kk << 5;  // 32B per k16 step
            uint32_t ah[2][4], al[2][4];
            #pragma unroll
            for (int mf = 0; mf < 2; ++mf) {
                const uint32_t ao = a_lm + mf * (16 * ROWB) + ko;
                LDSM_X4(ah[mf][0], ah[mf][1], ah[mf][2], ah[mf][3], sb + T_AHI + ao);
                LDSM_X4(al[mf][0], al[mf][1], al[mf][2], al[mf][3], sb + T_ALO + ao);
            }
            #pragma unroll
            for (int np = 0; np < 4; ++np) {
                uint32_t bh[4], bl[4];
                const uint32_t bo = b_lm + np * (16 * ROWB) + ko;
                LDSM_X4(bh[0], bh[1], bh[2], bh[3], sb + T_BHI + bo);
                LDSM_X4(bl[0], bl[1], bl[2], bl[3], sb + T_BLO + bo);
                #pragma unroll
                for (int mf = 0; mf < 2; ++mf) {
                    MMA_BF16(acc[mf][2 * np],     ah[mf], (&bh[0]));
                    MMA_BF16(acc[mf][2 * np],     ah[mf], (&bl[0]));
                    MMA_BF16(acc[mf][2 * np],     al[mf], (&bh[0]));
                    MMA_BF16(acc[mf][2 * np + 1], ah[mf], (&bh[2]));
                    MMA_BF16(acc[mf][2 * np + 1], ah[mf], (&bl[2]));
                    MMA_BF16(acc[mf][2 * np + 1], al[mf], (&bh[2]));
                }
            }
        }

        cbuf = (cbuf == NSTAGE - 1) ? 0 : cbuf + 1;
        lbuf = (lbuf == NSTAGE - 1) ? 0 : lbuf + 1;
    }

    // Epilogue: cosine scale + ReLU + store u + global max
    const int g  = lane >> 2;
    const int tg = lane & 3;
    float tmax = 0.f;
    #pragma unroll
    for (int mf = 0; mf < 2; ++mf) {
        const int ra = row0 + wm * 32 + mf * 16 + g;
        const float s0 = g_invx[ra];
        const float s1 = g_invx[ra + 8];
        #pragma unroll
        for (int nf = 0; nf < 8; ++nf) {
            const int col = col0 + wn * 64 + nf * 8 + tg * 2;
            const float w0 = g_invw[col];
            const float w1 = g_invw[col + 1];
            float2 v0, v1;
            v0.x = fmaxf(acc[mf][nf][0] * s0 * w0, 0.f);
            v0.y = fmaxf(acc[mf][nf][1] * s0 * w1, 0.f);
            v1.x = fmaxf(acc[mf][nf][2] * s1 * w0, 0.f);
            v1.y = fmaxf(acc[mf][nf][3] * s1 * w1, 0.f);
            tmax = fmaxf(tmax, fmaxf(fmaxf(v0.x, v0.y), fmaxf(v1.x, v1.y)));
            *reinterpret_cast<float2*>(&g_u[(size_t)ra * N + col])       = v0;
            *reinterpret_cast<float2*>(&g_u[(size_t)(ra + 8) * N + col]) = v1;
        }
    }

    #pragma unroll
    for (int o = 16; o; o >>= 1)
        tmax = fmaxf(tmax, __shfl_xor_sync(0xffffffffu, tmax, o));
    __shared__ float wmax[16];
    if (lane == 0) wmax[wid] = tmax;
    __syncthreads();
    if (tid == 0) {
        float m = wmax[0];
        #pragma unroll
        for (int i = 1; i < 16; ++i) m = fmaxf(m, wmax[i]);
        atomicMax(reinterpret_cast<int*>(&g_gmax), __float_as_int(m));
    }
}

// ---------------------------------------------------------------------------
// Kernel 3: per-row power-law + logprior + row-sum normalize.
// ---------------------------------------------------------------------------
__global__ void __launch_bounds__(256)
finalize_kernel(const float* __restrict__ logprior, const float* __restrict__ lamb_p,
                float* __restrict__ y, int N)
{
    const int r = blockIdx.x;
    const float lamb = lamb_p[0];
    const float inv_umax = 1.f / (g_gmax + EPSV);

    __shared__ float buf[O_DIM];
    const float4* u4  = reinterpret_cast<const float4*>(&g_u[(size_t)r * N]);
    const float4* lp4 = reinterpret_cast<const float4*>(logprior);
    float4* b4        = reinterpret_cast<float4*>(buf);

    const int n4 = N >> 2;
    float s = 0.f;
    for (int i = threadIdx.x; i < n4; i += blockDim.x) {
        float4 u = u4[i];
        float4 lp = lp4[i];
        float4 p;
        p.x = (u.x > 0.f) ? exp2f(lamb * log2f(u.x * inv_umax)) * expf(lp.x) : 0.f;
        p.y = (u.y > 0.f) ? exp2f(lamb * log2f(u.y * inv_umax)) * expf(lp.y) : 0.f;
        p.z = (u.z > 0.f) ? exp2f(lamb * log2f(u.z * inv_umax)) * expf(lp.z) : 0.f;
        p.w = (u.w > 0.f) ? exp2f(lamb * log2f(u.w * inv_umax)) * expf(lp.w) : 0.f;
        b4[i] = p;
        s += p.x + p.y + p.z + p.w;
    }

    #pragma unroll
    for (int o = 16; o; o >>= 1) s += __shfl_xor_sync(0xffffffffu, s, o);
    __shared__ float red[8];
    __shared__ float inv_sum_sh;
    const int lane = threadIdx.x & 31, wid = threadIdx.x >> 5;
    if (lane == 0) red[wid] = s;
    __syncthreads();
    if (threadIdx.x == 0) {
        float t = 0.f;
        for (int i = 0; i < 8; ++i) t += red[i];
        inv_sum_sh = 1.f / (t + EPSV);
    }
    __syncthreads();
    const float inv_sum = inv_sum_sh;

    float4* y4 = reinterpret_cast<float4*>(y + (size_t)r * N);
    for (int i = threadIdx.x; i < n4; i += blockDim.x) {
        float4 p = b4[i];
        p.x *= inv_sum; p.y *= inv_sum; p.z *= inv_sum; p.w *= inv_sum;
        y4[i] = p;
    }
}

// ---------------------------------------------------------------------------
// Launcher. Inputs: x [B,IN] f32, weight [OUT,IN] f32, logprior [OUT] f32,
// lamb [1] f32. Output: y [B,OUT] f32.
// ---------------------------------------------------------------------------
extern "C" void kernel_launch(void* const* d_in, const int* in_sizes, int n_in,
                              void* d_out, int out_size)
{
    const float* x        = (const float*)d_in[0];
    const float* w        = (const float*)d_in[1];
    const float* logprior = (const float*)d_in[2];
    const float* lamb     = (const float*)d_in[3];
    float* y              = (float*)d_out;

    const int OUT = in_sizes[2];
    const int IN  = in_sizes[1] / OUT;
    const int B   = in_sizes[0] / IN;

    cudaFuncSetAttribute(softhebb_mma_gemm,
                         cudaFuncAttributeMaxDynamicSharedMemorySize, DYN_SMEM);

    prep_kernel<<<B + OUT, 256>>>(x, w, B, OUT, IN);

    dim3 grid(OUT / 256, B / 128);
    softhebb_mma_gemm<<<grid, 512, DYN_SMEM>>>(B, OUT, IN);

    finalize_kernel<<<B, 256>>>(logprior, lamb, y, OUT);
}

// round 5
// speedup vs baseline: 2.6819x; 1.0054x over previous
#include <cuda_runtime.h>
#include <cuda_bf16.h>
#include <cstdint>

#define EPSV 1e-9f

// Fixed problem shape: B=16384, IN=K=2048, OUT=2048
#define B_DIM   16384
#define K_DIM   2048
#define O_DIM   2048

// ---------------------------------------------------------------------------
// Device scratch (no allocations allowed in kernel_launch)
// ---------------------------------------------------------------------------
__device__ float g_u[(size_t)B_DIM * O_DIM];      // relu(cos) scratch (128 MB)
__device__ float g_invx[B_DIM];
__device__ float g_invw[O_DIM];
__device__ float g_gmax;
__device__ __align__(16) __nv_bfloat16 g_xhi[(size_t)B_DIM * K_DIM];
__device__ __align__(16) __nv_bfloat16 g_xlo[(size_t)B_DIM * K_DIM];
__device__ __align__(16) __nv_bfloat16 g_whi[(size_t)O_DIM * K_DIM];
__device__ __align__(16) __nv_bfloat16 g_wlo[(size_t)O_DIM * K_DIM];

// ---------------------------------------------------------------------------
// PTX helpers (family-safe: ldmatrix, mma.sync, cp.async)
// ---------------------------------------------------------------------------
__device__ __forceinline__ uint32_t smem_u32(const void* p) {
    uint32_t a;
    asm("{ .reg .u64 t; cvta.to.shared.u64 t, %1; cvt.u32.u64 %0, t; }"
        : "=r"(a) : "l"(p));
    return a;
}

#define CP16(saddr, gptr) \
    asm volatile("cp.async.cg.shared.global [%0], [%1], 16;" \
                 :: "r"(saddr), "l"(gptr) : "memory")
#define CP_COMMIT() asm volatile("cp.async.commit_group;" ::: "memory")
#define CP_WAIT1()  asm volatile("cp.async.wait_group 1;" ::: "memory")

#define LDSM_X4(r0, r1, r2, r3, addr) \
    asm volatile("ldmatrix.sync.aligned.m8n8.x4.shared.b16 {%0,%1,%2,%3}, [%4];" \
                 : "=r"(r0), "=r"(r1), "=r"(r2), "=r"(r3) : "r"(addr))

#define MMA_BF16(d, a, b) \
    asm volatile("mma.sync.aligned.m16n8k16.row.col.f32.bf16.bf16.f32 " \
                 "{%0,%1,%2,%3}, {%4,%5,%6,%7}, {%8,%9}, {%0,%1,%2,%3};" \
                 : "+f"((d)[0]), "+f"((d)[1]), "+f"((d)[2]), "+f"((d)[3]) \
                 : "r"((a)[0]), "r"((a)[1]), "r"((a)[2]), "r"((a)[3]),   \
                   "r"((b)[0]), "r"((b)[1]))

// ---------------------------------------------------------------------------
// Kernel 1: fused per-row inv-norms + bf16 hi/lo split for x and W.
// ---------------------------------------------------------------------------
__global__ void __launch_bounds__(256)
prep_kernel(const float* __restrict__ x, const float* __restrict__ w,
            int B, int OUT, int IN)
{
    const int r = blockIdx.x;
    const float* src;
    __nv_bfloat16 *hi, *lo;
    float* dst;
    if (r < B) {
        src = x + (size_t)r * IN;
        hi = g_xhi + (size_t)r * IN; lo = g_xlo + (size_t)r * IN;
        dst = &g_invx[r];
    } else {
        const int rr = r - B;
        src = w + (size_t)rr * IN;
        hi = g_whi + (size_t)rr * IN; lo = g_wlo + (size_t)rr * IN;
        dst = &g_invw[rr];
    }

    float s = 0.f;
    const float4* p4 = reinterpret_cast<const float4*>(src);
    uint2* h2 = reinterpret_cast<uint2*>(hi);
    uint2* l2 = reinterpret_cast<uint2*>(lo);
    const int n4 = IN >> 2;
    for (int i = threadIdx.x; i < n4; i += blockDim.x) {
        float4 v = p4[i];
        s += v.x * v.x + v.y * v.y + v.z * v.z + v.w * v.w;
        __nv_bfloat16 ha = __float2bfloat16_rn(v.x);
        __nv_bfloat16 hb = __float2bfloat16_rn(v.y);
        __nv_bfloat16 hc = __float2bfloat16_rn(v.z);
        __nv_bfloat16 hd = __float2bfloat16_rn(v.w);
        __nv_bfloat16 la = __float2bfloat16_rn(v.x - __bfloat162float(ha));
        __nv_bfloat16 lb = __float2bfloat16_rn(v.y - __bfloat162float(hb));
        __nv_bfloat16 lc = __float2bfloat16_rn(v.z - __bfloat162float(hc));
        __nv_bfloat16 ld = __float2bfloat16_rn(v.w - __bfloat162float(hd));
        uint2 uh, ul;
        uh.x = (uint32_t)__bfloat16_as_ushort(ha) | ((uint32_t)__bfloat16_as_ushort(hb) << 16);
        uh.y = (uint32_t)__bfloat16_as_ushort(hc) | ((uint32_t)__bfloat16_as_ushort(hd) << 16);
        ul.x = (uint32_t)__bfloat16_as_ushort(la) | ((uint32_t)__bfloat16_as_ushort(lb) << 16);
        ul.y = (uint32_t)__bfloat16_as_ushort(lc) | ((uint32_t)__bfloat16_as_ushort(ld) << 16);
        h2[i] = uh;
        l2[i] = ul;
    }

    #pragma unroll
    for (int o = 16; o; o >>= 1) s += __shfl_xor_sync(0xffffffffu, s, o);
    __shared__ float red[8];
    const int lane = threadIdx.x & 31, wid = threadIdx.x >> 5;
    if (lane == 0) red[wid] = s;
    __syncthreads();
    if (threadIdx.x == 0) {
        float t = 0.f;
        for (int i = 0; i < 8; ++i) t += red[i];
        *dst = 1.f / (sqrtf(t) + EPSV);
        if (r == 0) g_gmax = 0.f;
    }
}

// ---------------------------------------------------------------------------
// Kernel 2: mma.sync bf16 3-term split GEMM + fused cosine/ReLU/max epilogue.
// CTA 128x256, 256 threads, 8 warps (2 M x 4 N), warp tile 64x64.
// K chunks of 32, cp.async 3-stage pipeline, one __syncthreads per chunk.
// SMEM per stage: Ahi/Alo 128x80B, Bhi/Blo 256x80B (64B data + 16B pad).
// 80B row stride => conflict-free ldmatrix.
// ---------------------------------------------------------------------------
#define ROWB     80
#define T_AHI    0
#define T_ALO    10240
#define T_BHI    20480
#define T_BLO    40960
#define STAGE_SZ 61440
#define NSTAGE   3
#define DYN_SMEM (NSTAGE * STAGE_SZ)

__global__ void __launch_bounds__(256, 1)
softhebb_mma_gemm(int M, int N, int K)
{
    extern __shared__ char sm[];
    const uint32_t sbase = smem_u32(sm);

    const int tid  = threadIdx.x;
    const int wid  = tid >> 5;
    const int lane = tid & 31;
    const int wm   = wid & 1;   // M warp (0..1): rows wm*64..+63
    const int wn   = wid >> 1;  // N warp (0..3): cols wn*64..+63

    const int row0 = blockIdx.y * 128;
    const int col0 = blockIdx.x * 256;

    float acc[4][8][4];
    #pragma unroll
    for (int i = 0; i < 4; ++i)
        #pragma unroll
        for (int j = 0; j < 8; ++j)
            #pragma unroll
            for (int q = 0; q < 4; ++q) acc[i][j][q] = 0.f;

    const int nchunks = K >> 5;  // 64

    // ldmatrix base addresses (within a stage)
    const uint32_t a_lm = (uint32_t)((wm * 64 + (lane & 15)) * ROWB + (lane >> 4) * 16);
    const uint32_t b_lm = (uint32_t)((wn * 64 + (lane & 7) + ((lane >> 4) << 3)) * ROWB
                                     + (((lane >> 3) & 1) << 4));

    // Per-stage load with 256 threads: A 512 x 16B chunks/matrix (2/thread),
    // B 1024 chunks/matrix (4/thread) -> 12 CP16 per thread.
    #define LOAD_STAGE(chunk, stg) do {                                          \
        const int kel = (chunk) << 5;                                            \
        const uint32_t sb_ = sbase + (stg) * STAGE_SZ;                           \
        _Pragma("unroll")                                                        \
        for (int t = 0; t < 2; ++t) {                                            \
            const int c_ = tid + (t << 8);                                       \
            const int r = c_ >> 2, q = c_ & 3;                                   \
            const uint32_t so = (uint32_t)(r * ROWB + q * 16);                   \
            const size_t ga = (size_t)(row0 + r) * K + kel + q * 8;              \
            CP16(sb_ + T_AHI + so, g_xhi + ga);                                  \
            CP16(sb_ + T_ALO + so, g_xlo + ga);                                  \
        }                                                                        \
        _Pragma("unroll")                                                        \
        for (int t = 0; t < 4; ++t) {                                            \
            const int c_ = tid + (t << 8);                                       \
            const int r = c_ >> 2, q = c_ & 3;                                   \
            const uint32_t so = (uint32_t)(r * ROWB + q * 16);                   \
            const size_t gb = (size_t)(col0 + r) * K + kel + q * 8;              \
            CP16(sb_ + T_BHI + so, g_whi + gb);                                  \
            CP16(sb_ + T_BLO + so, g_wlo + gb);                                  \
        }                                                                        \
    } while (0)

    LOAD_STAGE(0, 0);
    CP_COMMIT();
    LOAD_STAGE(1, 1);
    CP_COMMIT();

    int cbuf = 0, lbuf = 2;
    for (int c = 0; c < nchunks; ++c) {
        CP_WAIT1();          // chunk c resident
        __syncthreads();     // all warps past compute(c-1); safe to overwrite lbuf

        if (c + 2 < nchunks) LOAD_STAGE(c + 2, lbuf);
        CP_COMMIT();         // commit every iter keeps group accounting uniform

        const uint32_t sb = sbase + cbuf * STAGE_SZ;
        #pragma unroll
        for (int kk = 0; kk < 2; ++kk) {
            const uint32_t ko = kk << 5;  // 32B per k16 step
            uint32_t ah[4][4], al[4][4];
            #pragma unroll
            for (int mf = 0; mf < 4; ++mf) {
                const uint32_t ao = a_lm + mf * (16 * ROWB) + ko;
                LDSM_X4(ah[mf][0], ah[mf][1], ah[mf][2], ah[mf][3], sb + T_AHI + ao);
                LDSM_X4(al[mf][0], al[mf][1], al[mf][2], al[mf][3], sb + T_ALO + ao);
            }
            #pragma unroll
            for (int np = 0; np < 4; ++np) {
                uint32_t bh[4], bl[4];
                const uint32_t bo = b_lm + np * (16 * ROWB) + ko;
                LDSM_X4(bh[0], bh[1], bh[2], bh[3], sb + T_BHI + bo);
                LDSM_X4(bl[0], bl[1], bl[2], bl[3], sb + T_BLO + bo);
                #pragma unroll
                for (int mf = 0; mf < 4; ++mf) {
                    MMA_BF16(acc[mf][2 * np],     ah[mf], (&bh[0]));
                    MMA_BF16(acc[mf][2 * np],     ah[mf], (&bl[0]));
                    MMA_BF16(acc[mf][2 * np],     al[mf], (&bh[0]));
                    MMA_BF16(acc[mf][2 * np + 1], ah[mf], (&bh[2]));
                    MMA_BF16(acc[mf][2 * np + 1], ah[mf], (&bl[2]));
                    MMA_BF16(acc[mf][2 * np + 1], al[mf], (&bh[2]));
                }
            }
        }

        cbuf = (cbuf == NSTAGE - 1) ? 0 : cbuf + 1;
        lbuf = (lbuf == NSTAGE - 1) ? 0 : lbuf + 1;
    }

    // Epilogue: cosine scale + ReLU + store u + global max
    const int g  = lane >> 2;
    const int tg = lane & 3;
    float tmax = 0.f;
    #pragma unroll
    for (int mf = 0; mf < 4; ++mf) {
        const int ra = row0 + wm * 64 + mf * 16 + g;
        const float s0 = g_invx[ra];
        const float s1 = g_invx[ra + 8];
        #pragma unroll
        for (int nf = 0; nf < 8; ++nf) {
            const int col = col0 + wn * 64 + nf * 8 + tg * 2;
            const float w0 = g_invw[col];
            const float w1 = g_invw[col + 1];
            float2 v0, v1;
            v0.x = fmaxf(acc[mf][nf][0] * s0 * w0, 0.f);
            v0.y = fmaxf(acc[mf][nf][1] * s0 * w1, 0.f);
            v1.x = fmaxf(acc[mf][nf][2] * s1 * w0, 0.f);
            v1.y = fmaxf(acc[mf][nf][3] * s1 * w1, 0.f);
            tmax = fmaxf(tmax, fmaxf(fmaxf(v0.x, v0.y), fmaxf(v1.x, v1.y)));
            *reinterpret_cast<float2*>(&g_u[(size_t)ra * N + col])       = v0;
            *reinterpret_cast<float2*>(&g_u[(size_t)(ra + 8) * N + col]) = v1;
        }
    }

    #pragma unroll
    for (int o = 16; o; o >>= 1)
        tmax = fmaxf(tmax, __shfl_xor_sync(0xffffffffu, tmax, o));
    __shared__ float wmax[8];
    if (lane == 0) wmax[wid] = tmax;
    __syncthreads();
    if (tid == 0) {
        float m = wmax[0];
        #pragma unroll
        for (int i = 1; i < 8; ++i) m = fmaxf(m, wmax[i]);
        atomicMax(reinterpret_cast<int*>(&g_gmax), __float_as_int(m));
    }
}

// ---------------------------------------------------------------------------
// Kernel 3: per-row power-law + logprior + row-sum normalize.
// ---------------------------------------------------------------------------
__global__ void __launch_bounds__(256)
finalize_kernel(const float* __restrict__ logprior, const float* __restrict__ lamb_p,
                float* __restrict__ y, int N)
{
    const int r = blockIdx.x;
    const float lamb = lamb_p[0];
    const float inv_umax = 1.f / (g_gmax + EPSV);

    __shared__ float buf[O_DIM];
    const float4* u4  = reinterpret_cast<const float4*>(&g_u[(size_t)r * N]);
    const float4* lp4 = reinterpret_cast<const float4*>(logprior);
    float4* b4        = reinterpret_cast<float4*>(buf);

    const int n4 = N >> 2;
    float s = 0.f;
    for (int i = threadIdx.x; i < n4; i += blockDim.x) {
        float4 u = u4[i];
        float4 lp = lp4[i];
        float4 p;
        p.x = (u.x > 0.f) ? exp2f(lamb * log2f(u.x * inv_umax)) * expf(lp.x) : 0.f;
        p.y = (u.y > 0.f) ? exp2f(lamb * log2f(u.y * inv_umax)) * expf(lp.y) : 0.f;
        p.z = (u.z > 0.f) ? exp2f(lamb * log2f(u.z * inv_umax)) * expf(lp.z) : 0.f;
        p.w = (u.w > 0.f) ? exp2f(lamb * log2f(u.w * inv_umax)) * expf(lp.w) : 0.f;
        b4[i] = p;
        s += p.x + p.y + p.z + p.w;
    }

    #pragma unroll
    for (int o = 16; o; o >>= 1) s += __shfl_xor_sync(0xffffffffu, s, o);
    __shared__ float red[8];
    __shared__ float inv_sum_sh;
    const int lane = threadIdx.x & 31, wid = threadIdx.x >> 5;
    if (lane == 0) red[wid] = s;
    __syncthreads();
    if (threadIdx.x == 0) {
        float t = 0.f;
        for (int i = 0; i < 8; ++i) t += red[i];
        inv_sum_sh = 1.f / (t + EPSV);
    }
    __syncthreads();
    const float inv_sum = inv_sum_sh;

    float4* y4 = reinterpret_cast<float4*>(y + (size_t)r * N);
    for (int i = threadIdx.x; i < n4; i += blockDim.x) {
        float4 p = b4[i];
        p.x *= inv_sum; p.y *= inv_sum; p.z *= inv_sum; p.w *= inv_sum;
        y4[i] = p;
    }
}

// ---------------------------------------------------------------------------
// Launcher. Inputs: x [B,IN] f32, weight [OUT,IN] f32, logprior [OUT] f32,
// lamb [1] f32. Output: y [B,OUT] f32.
// ---------------------------------------------------------------------------
extern "C" void kernel_launch(void* const* d_in, const int* in_sizes, int n_in,
                              void* d_out, int out_size)
{
    const float* x        = (const float*)d_in[0];
    const float* w        = (const float*)d_in[1];
    const float* logprior = (const float*)d_in[2];
    const float* lamb     = (const float*)d_in[3];
    float* y              = (float*)d_out;

    const int OUT = in_sizes[2];
    const int IN  = in_sizes[1] / OUT;
    const int B   = in_sizes[0] / IN;

    cudaFuncSetAttribute(softhebb_mma_gemm,
                         cudaFuncAttributeMaxDynamicSharedMemorySize, DYN_SMEM);

    prep_kernel<<<B + OUT, 256>>>(x, w, B, OUT, IN);

    dim3 grid(OUT / 256, B / 128);
    softhebb_mma_gemm<<<grid, 256, DYN_SMEM>>>(B, OUT, IN);

    finalize_kernel<<<B, 256>>>(logprior, lamb, y, OUT);
}

// round 6
// speedup vs baseline: 6.2723x; 2.3388x over previous
#include <cuda_runtime.h>
#include <cuda_fp16.h>
#include <cstdint>

#define EPSV 1e-9f

// Fixed problem shape: B=16384, IN=K=2048, OUT=2048
#define B_DIM   16384
#define K_DIM   2048
#define O_DIM   2048

// ---------------------------------------------------------------------------
// Device scratch (no allocations allowed in kernel_launch)
// ---------------------------------------------------------------------------
__device__ float g_u[(size_t)B_DIM * O_DIM];      // relu(cos) scratch (128 MB)
__device__ float g_gmax;
__device__ __align__(16) __half g_xh[(size_t)B_DIM * K_DIM];  // normalized x, fp16
__device__ __align__(16) __half g_wh[(size_t)O_DIM * K_DIM];  // normalized w, fp16

// ---------------------------------------------------------------------------
// PTX helpers (family-safe: ldmatrix, mma.sync, cp.async)
// ---------------------------------------------------------------------------
__device__ __forceinline__ uint32_t smem_u32(const void* p) {
    uint32_t a;
    asm("{ .reg .u64 t; cvta.to.shared.u64 t, %1; cvt.u32.u64 %0, t; }"
        : "=r"(a) : "l"(p));
    return a;
}

#define CP16(saddr, gptr) \
    asm volatile("cp.async.cg.shared.global [%0], [%1], 16;" \
                 :: "r"(saddr), "l"(gptr) : "memory")
#define CP_COMMIT() asm volatile("cp.async.commit_group;" ::: "memory")
#define CP_WAIT1()  asm volatile("cp.async.wait_group 1;" ::: "memory")

#define LDSM_X4(r0, r1, r2, r3, addr) \
    asm volatile("ldmatrix.sync.aligned.m8n8.x4.shared.b16 {%0,%1,%2,%3}, [%4];" \
                 : "=r"(r0), "=r"(r1), "=r"(r2), "=r"(r3) : "r"(addr))

#define MMA_F16(d, a, b) \
    asm volatile("mma.sync.aligned.m16n8k16.row.col.f32.f16.f16.f32 " \
                 "{%0,%1,%2,%3}, {%4,%5,%6,%7}, {%8,%9}, {%0,%1,%2,%3};" \
                 : "+f"((d)[0]), "+f"((d)[1]), "+f"((d)[2]), "+f"((d)[3]) \
                 : "r"((a)[0]), "r"((a)[1]), "r"((a)[2]), "r"((a)[3]),   \
                   "r"((b)[0]), "r"((b)[1]))

// ---------------------------------------------------------------------------
// Kernel 1: per-row L2 normalize -> fp16. Two-pass via smem row buffer.
// Blocks [0,B): x rows -> g_xh; [B,B+OUT): w rows -> g_wh. Resets g_gmax.
// ---------------------------------------------------------------------------
__global__ void __launch_bounds__(256)
prep_kernel(const float* __restrict__ x, const float* __restrict__ w,
            int B, int OUT, int IN)
{
    __shared__ float rowbuf[K_DIM];
    const int r = blockIdx.x;
    const float* src;
    __half* dst;
    if (r < B) { src = x + (size_t)r * IN;       dst = g_xh + (size_t)r * IN; }
    else       { src = w + (size_t)(r - B) * IN; dst = g_wh + (size_t)(r - B) * IN; }

    float s = 0.f;
    const float4* p4 = reinterpret_cast<const float4*>(src);
    float4* b4 = reinterpret_cast<float4*>(rowbuf);
    const int n4 = IN >> 2;
    for (int i = threadIdx.x; i < n4; i += blockDim.x) {
        float4 v = p4[i];
        b4[i] = v;
        s += v.x * v.x + v.y * v.y + v.z * v.z + v.w * v.w;
    }

    #pragma unroll
    for (int o = 16; o; o >>= 1) s += __shfl_xor_sync(0xffffffffu, s, o);
    __shared__ float red[8];
    __shared__ float scale_sh;
    const int lane = threadIdx.x & 31, wid = threadIdx.x >> 5;
    if (lane == 0) red[wid] = s;
    __syncthreads();
    if (threadIdx.x == 0) {
        float t = 0.f;
        for (int i = 0; i < 8; ++i) t += red[i];
        scale_sh = 1.f / (sqrtf(t) + EPSV);
        if (r == 0) g_gmax = 0.f;
    }
    __syncthreads();
    const float sc = scale_sh;

    uint2* d2 = reinterpret_cast<uint2*>(dst);
    for (int i = threadIdx.x; i < n4; i += blockDim.x) {
        float4 v = b4[i];
        __half2 lo = __floats2half2_rn(v.x * sc, v.y * sc);
        __half2 hi = __floats2half2_rn(v.z * sc, v.w * sc);
        uint2 u;
        u.x = *reinterpret_cast<uint32_t*>(&lo);
        u.y = *reinterpret_cast<uint32_t*>(&hi);
        d2[i] = u;
    }
}

// ---------------------------------------------------------------------------
// Kernel 2: single-term fp16 mma.sync GEMM + fused ReLU/max epilogue.
// CTA 128x256, 256 threads, 8 warps (2 M x 4 N), warp tile 64x64.
// K chunks of 64, cp.async 3-stage pipeline, one __syncthreads per chunk.
// SMEM per stage: A 128x144B, B 256x144B (128B data + 16B pad).
// 144B row stride (9 x 16B) => conflict-free ldmatrix.
// ---------------------------------------------------------------------------
#define ROWB     144
#define T_A      0
#define T_B      18432
#define STAGE_SZ 55296
#define NSTAGE   3
#define DYN_SMEM (NSTAGE * STAGE_SZ)

__global__ void __launch_bounds__(256, 1)
softhebb_mma_gemm(int M, int N, int K)
{
    extern __shared__ char sm[];
    const uint32_t sbase = smem_u32(sm);

    const int tid  = threadIdx.x;
    const int wid  = tid >> 5;
    const int lane = tid & 31;
    const int wm   = wid & 1;   // M warp (0..1): rows wm*64..+63
    const int wn   = wid >> 1;  // N warp (0..3): cols wn*64..+63

    const int row0 = blockIdx.y * 128;
    const int col0 = blockIdx.x * 256;

    float acc[4][8][4];
    #pragma unroll
    for (int i = 0; i < 4; ++i)
        #pragma unroll
        for (int j = 0; j < 8; ++j)
            #pragma unroll
            for (int q = 0; q < 4; ++q) acc[i][j][q] = 0.f;

    const int nchunks = K >> 6;  // 32

    // ldmatrix base addresses (within a stage)
    const uint32_t a_lm = (uint32_t)((wm * 64 + (lane & 15)) * ROWB + (lane >> 4) * 16);
    const uint32_t b_lm = (uint32_t)((wn * 64 + (lane & 7) + ((lane >> 4) << 3)) * ROWB
                                     + (((lane >> 3) & 1) << 4));

    // Per-stage load, 256 threads: A 1024 x 16B chunks (4/thread),
    // B 2048 chunks (8/thread) -> 12 CP16 per thread.
    #define LOAD_STAGE(chunk, stg) do {                                          \
        const int kel = (chunk) << 6;                                            \
        const uint32_t sb_ = sbase + (stg) * STAGE_SZ;                           \
        _Pragma("unroll")                                                        \
        for (int t = 0; t < 4; ++t) {                                            \
            const int c_ = tid + (t << 8);                                       \
            const int rr = c_ >> 3, q = c_ & 7;                                  \
            const uint32_t so = (uint32_t)(rr * ROWB + q * 16);                  \
            const size_t ga = (size_t)(row0 + rr) * K + kel + q * 8;             \
            CP16(sb_ + T_A + so, g_xh + ga);                                     \
        }                                                                        \
        _Pragma("unroll")                                                        \
        for (int t = 0; t < 8; ++t) {                                            \
            const int c_ = tid + (t << 8);                                       \
            const int rr = c_ >> 3, q = c_ & 7;                                  \
            const uint32_t so = (uint32_t)(rr * ROWB + q * 16);                  \
            const size_t gb = (size_t)(col0 + rr) * K + kel + q * 8;             \
            CP16(sb_ + T_B + so, g_wh + gb);                                     \
        }                                                                        \
    } while (0)

    LOAD_STAGE(0, 0);
    CP_COMMIT();
    LOAD_STAGE(1, 1);
    CP_COMMIT();

    int cbuf = 0, lbuf = 2;
    for (int c = 0; c < nchunks; ++c) {
        CP_WAIT1();          // chunk c resident
        __syncthreads();     // all warps past compute(c-1); safe to overwrite lbuf

        if (c + 2 < nchunks) LOAD_STAGE(c + 2, lbuf);
        CP_COMMIT();         // commit every iter keeps group accounting uniform

        const uint32_t sb = sbase + cbuf * STAGE_SZ;
        #pragma unroll
        for (int kk = 0; kk < 4; ++kk) {
            const uint32_t ko = kk << 5;  // 32B per k16 step
            uint32_t ah[4][4];
            #pragma unroll
            for (int mf = 0; mf < 4; ++mf) {
                const uint32_t ao = a_lm + mf * (16 * ROWB) + ko;
                LDSM_X4(ah[mf][0], ah[mf][1], ah[mf][2], ah[mf][3], sb + T_A + ao);
            }
            #pragma unroll
            for (int np = 0; np < 4; ++np) {
                uint32_t bh[4];
                const uint32_t bo = b_lm + np * (16 * ROWB) + ko;
                LDSM_X4(bh[0], bh[1], bh[2], bh[3], sb + T_B + bo);
                #pragma unroll
                for (int mf = 0; mf < 4; ++mf) {
                    MMA_F16(acc[mf][2 * np],     ah[mf], (&bh[0]));
                    MMA_F16(acc[mf][2 * np + 1], ah[mf], (&bh[2]));
                }
            }
        }

        cbuf = (cbuf == NSTAGE - 1) ? 0 : cbuf + 1;
        lbuf = (lbuf == NSTAGE - 1) ? 0 : lbuf + 1;
    }

    // Epilogue: ReLU + store u + global max (operands pre-normalized)
    const int g  = lane >> 2;
    const int tg = lane & 3;
    float tmax = 0.f;
    #pragma unroll
    for (int mf = 0; mf < 4; ++mf) {
        const int ra = row0 + wm * 64 + mf * 16 + g;
        #pragma unroll
        for (int nf = 0; nf < 8; ++nf) {
            const int col = col0 + wn * 64 + nf * 8 + tg * 2;
            float2 v0, v1;
            v0.x = fmaxf(acc[mf][nf][0], 0.f);
            v0.y = fmaxf(acc[mf][nf][1], 0.f);
            v1.x = fmaxf(acc[mf][nf][2], 0.f);
            v1.y = fmaxf(acc[mf][nf][3], 0.f);
            tmax = fmaxf(tmax, fmaxf(fmaxf(v0.x, v0.y), fmaxf(v1.x, v1.y)));
            *reinterpret_cast<float2*>(&g_u[(size_t)ra * N + col])       = v0;
            *reinterpret_cast<float2*>(&g_u[(size_t)(ra + 8) * N + col]) = v1;
        }
    }

    #pragma unroll
    for (int o = 16; o; o >>= 1)
        tmax = fmaxf(tmax, __shfl_xor_sync(0xffffffffu, tmax, o));
    __shared__ float wmax[8];
    if (lane == 0) wmax[wid] = tmax;
    __syncthreads();
    if (tid == 0) {
        float m = wmax[0];
        #pragma unroll
        for (int i = 1; i < 8; ++i) m = fmaxf(m, wmax[i]);
        atomicMax(reinterpret_cast<int*>(&g_gmax), __float_as_int(m));
    }
}

// ---------------------------------------------------------------------------
// Kernel 3: per-row power-law + logprior + row-sum normalize.
// ---------------------------------------------------------------------------
__global__ void __launch_bounds__(256)
finalize_kernel(const float* __restrict__ logprior, const float* __restrict__ lamb_p,
                float* __restrict__ y, int N)
{
    const int r = blockIdx.x;
    const float lamb = lamb_p[0];
    const float inv_umax = 1.f / (g_gmax + EPSV);

    __shared__ float buf[O_DIM];
    const float4* u4  = reinterpret_cast<const float4*>(&g_u[(size_t)r * N]);
    const float4* lp4 = reinterpret_cast<const float4*>(logprior);
    float4* b4        = reinterpret_cast<float4*>(buf);

    const int n4 = N >> 2;
    float s = 0.f;
    for (int i = threadIdx.x; i < n4; i += blockDim.x) {
        float4 u = u4[i];
        float4 lp = lp4[i];
        float4 p;
        p.x = (u.x > 0.f) ? exp2f(lamb * log2f(u.x * inv_umax)) * expf(lp.x) : 0.f;
        p.y = (u.y > 0.f) ? exp2f(lamb * log2f(u.y * inv_umax)) * expf(lp.y) : 0.f;
        p.z = (u.z > 0.f) ? exp2f(lamb * log2f(u.z * inv_umax)) * expf(lp.z) : 0.f;
        p.w = (u.w > 0.f) ? exp2f(lamb * log2f(u.w * inv_umax)) * expf(lp.w) : 0.f;
        b4[i] = p;
        s += p.x + p.y + p.z + p.w;
    }

    #pragma unroll
    for (int o = 16; o; o >>= 1) s += __shfl_xor_sync(0xffffffffu, s, o);
    __shared__ float red[8];
    __shared__ float inv_sum_sh;
    const int lane = threadIdx.x & 31, wid = threadIdx.x >> 5;
    if (lane == 0) red[wid] = s;
    __syncthreads();
    if (threadIdx.x == 0) {
        float t = 0.f;
        for (int i = 0; i < 8; ++i) t += red[i];
        inv_sum_sh = 1.f / (t + EPSV);
    }
    __syncthreads();
    const float inv_sum = inv_sum_sh;

    float4* y4 = reinterpret_cast<float4*>(y + (size_t)r * N);
    for (int i = threadIdx.x; i < n4; i += blockDim.x) {
        float4 p = b4[i];
        p.x *= inv_sum; p.y *= inv_sum; p.z *= inv_sum; p.w *= inv_sum;
        y4[i] = p;
    }
}

// ---------------------------------------------------------------------------
// Launcher. Inputs: x [B,IN] f32, weight [OUT,IN] f32, logprior [OUT] f32,
// lamb [1] f32. Output: y [B,OUT] f32.
// ---------------------------------------------------------------------------
extern "C" void kernel_launch(void* const* d_in, const int* in_sizes, int n_in,
                              void* d_out, int out_size)
{
    const float* x        = (const float*)d_in[0];
    const float* w        = (const float*)d_in[1];
    const float* logprior = (const float*)d_in[2];
    const float* lamb     = (const float*)d_in[3];
    float* y              = (float*)d_out;

    const int OUT = in_sizes[2];
    const int IN  = in_sizes[1] / OUT;
    const int B   = in_sizes[0] / IN;

    cudaFuncSetAttribute(softhebb_mma_gemm,
                         cudaFuncAttributeMaxDynamicSharedMemorySize, DYN_SMEM);

    prep_kernel<<<B + OUT, 256>>>(x, w, B, OUT, IN);

    dim3 grid(OUT / 256, B / 128);
    softhebb_mma_gemm<<<grid, 256, DYN_SMEM>>>(B, OUT, IN);

    finalize_kernel<<<B, 256>>>(logprior, lamb, y, OUT);
}

// round 7
// speedup vs baseline: 6.3529x; 1.0128x over previous
#include <cuda_runtime.h>
#include <cuda_fp16.h>
#include <cstdint>

#define EPSV 1e-9f

// Fixed problem shape: B=16384, IN=K=2048, OUT=2048
#define B_DIM   16384
#define K_DIM   2048
#define O_DIM   2048

// ---------------------------------------------------------------------------
// Device scratch (no allocations allowed in kernel_launch)
// ---------------------------------------------------------------------------
__device__ float g_u[(size_t)B_DIM * O_DIM];      // relu(cos) scratch (128 MB)
__device__ float g_gmax;
__device__ __align__(16) __half g_xh[(size_t)B_DIM * K_DIM];  // normalized x, fp16
__device__ __align__(16) __half g_wh[(size_t)O_DIM * K_DIM];  // normalized w, fp16

// ---------------------------------------------------------------------------
// PTX helpers (family-safe: ldmatrix, mma.sync, cp.async)
// ---------------------------------------------------------------------------
__device__ __forceinline__ uint32_t smem_u32(const void* p) {
    uint32_t a;
    asm("{ .reg .u64 t; cvta.to.shared.u64 t, %1; cvt.u32.u64 %0, t; }"
        : "=r"(a) : "l"(p));
    return a;
}

#define CP16(saddr, gptr) \
    asm volatile("cp.async.cg.shared.global [%0], [%1], 16;" \
                 :: "r"(saddr), "l"(gptr) : "memory")
#define CP_COMMIT() asm volatile("cp.async.commit_group;" ::: "memory")
#define CP_WAIT1()  asm volatile("cp.async.wait_group 1;" ::: "memory")

#define LDSM_X4(r0, r1, r2, r3, addr) \
    asm volatile("ldmatrix.sync.aligned.m8n8.x4.shared.b16 {%0,%1,%2,%3}, [%4];" \
                 : "=r"(r0), "=r"(r1), "=r"(r2), "=r"(r3) : "r"(addr))

#define MMA_F16(d, a, b) \
    asm volatile("mma.sync.aligned.m16n8k16.row.col.f32.f16.f16.f32 " \
                 "{%0,%1,%2,%3}, {%4,%5,%6,%7}, {%8,%9}, {%0,%1,%2,%3};" \
                 : "+f"((d)[0]), "+f"((d)[1]), "+f"((d)[2]), "+f"((d)[3]) \
                 : "r"((a)[0]), "r"((a)[1]), "r"((a)[2]), "r"((a)[3]),   \
                   "r"((b)[0]), "r"((b)[1]))

// ---------------------------------------------------------------------------
// Kernel 1: per-row L2 normalize -> fp16. Row held in registers (8 float4).
// Blocks [0,B): x rows -> g_xh; [B,B+OUT): w rows -> g_wh. Resets g_gmax.
// ---------------------------------------------------------------------------
__global__ void __launch_bounds__(256)
prep_kernel(const float* __restrict__ x, const float* __restrict__ w,
            int B, int OUT, int IN)
{
    const int r = blockIdx.x;
    const float* src;
    __half* dst;
    if (r < B) { src = x + (size_t)r * IN;       dst = g_xh + (size_t)r * IN; }
    else       { src = w + (size_t)(r - B) * IN; dst = g_wh + (size_t)(r - B) * IN; }

    const float4* p4 = reinterpret_cast<const float4*>(src);
    float4 v[8];   // 2048 / (256 threads * 4) = 2 ... actually 2048/4/256 = 2; keep generic 8
    const int n4 = IN >> 2;        // 512
    const int nit = n4 / 256;      // 2 for IN=2048

    float s = 0.f;
    #pragma unroll
    for (int j = 0; j < 8; ++j) {
        if (j < nit) {
            v[j] = p4[threadIdx.x + j * 256];
            s += v[j].x * v[j].x + v[j].y * v[j].y + v[j].z * v[j].z + v[j].w * v[j].w;
        }
    }

    #pragma unroll
    for (int o = 16; o; o >>= 1) s += __shfl_xor_sync(0xffffffffu, s, o);
    __shared__ float red[8];
    __shared__ float scale_sh;
    const int lane = threadIdx.x & 31, wid = threadIdx.x >> 5;
    if (lane == 0) red[wid] = s;
    __syncthreads();
    if (threadIdx.x == 0) {
        float t = 0.f;
        for (int i = 0; i < 8; ++i) t += red[i];
        scale_sh = 1.f / (sqrtf(t) + EPSV);
        if (r == 0) g_gmax = 0.f;
    }
    __syncthreads();
    const float sc = scale_sh;

    uint2* d2 = reinterpret_cast<uint2*>(dst);
    #pragma unroll
    for (int j = 0; j < 8; ++j) {
        if (j < nit) {
            __half2 lo = __floats2half2_rn(v[j].x * sc, v[j].y * sc);
            __half2 hi = __floats2half2_rn(v[j].z * sc, v[j].w * sc);
            uint2 u;
            u.x = *reinterpret_cast<uint32_t*>(&lo);
            u.y = *reinterpret_cast<uint32_t*>(&hi);
            d2[threadIdx.x + j * 256] = u;
        }
    }
}

// ---------------------------------------------------------------------------
// Kernel 2: single-term fp16 mma.sync GEMM + fused ReLU/max epilogue.
// CTA 128x256, 512 threads, 16 warps (2 M x 8 N), warp tile 64x32.
// K chunks of 64, cp.async 3-stage pipeline, one __syncthreads per chunk.
// SMEM per stage: A 128x144B, B 256x144B (128B data + 16B pad).
// 144B row stride (9 x 16B) => conflict-free ldmatrix.
// ---------------------------------------------------------------------------
#define ROWB     144
#define T_A      0
#define T_B      18432
#define STAGE_SZ 55296
#define NSTAGE   3
#define DYN_SMEM (NSTAGE * STAGE_SZ)

__global__ void __launch_bounds__(512, 1)
softhebb_mma_gemm(int M, int N, int K)
{
    extern __shared__ char sm[];
    const uint32_t sbase = smem_u32(sm);

    const int tid  = threadIdx.x;
    const int wid  = tid >> 5;
    const int lane = tid & 31;
    const int wm   = wid & 1;   // M warp (0..1): rows wm*64..+63
    const int wn   = wid >> 1;  // N warp (0..7): cols wn*32..+31

    const int row0 = blockIdx.y * 128;
    const int col0 = blockIdx.x * 256;

    float acc[4][4][4];   // [mf(m16)][nf(n8)][quad]
    #pragma unroll
    for (int i = 0; i < 4; ++i)
        #pragma unroll
        for (int j = 0; j < 4; ++j)
            #pragma unroll
            for (int q = 0; q < 4; ++q) acc[i][j][q] = 0.f;

    const int nchunks = K >> 6;  // 32

    // ldmatrix base addresses (within a stage)
    const uint32_t a_lm = (uint32_t)((wm * 64 + (lane & 15)) * ROWB + (lane >> 4) * 16);
    const uint32_t b_lm = (uint32_t)((wn * 32 + (lane & 7) + ((lane >> 4) << 3)) * ROWB
                                     + (((lane >> 3) & 1) << 4));

    // Per-stage load, 512 threads: A 1024 x 16B chunks (2/thread),
    // B 2048 chunks (4/thread) -> 6 CP16 per thread.
    #define LOAD_STAGE(chunk, stg) do {                                          \
        const int kel = (chunk) << 6;                                            \
        const uint32_t sb_ = sbase + (stg) * STAGE_SZ;                           \
        _Pragma("unroll")                                                        \
        for (int t = 0; t < 2; ++t) {                                            \
            const int c_ = tid + (t << 9);                                       \
            const int rr = c_ >> 3, q = c_ & 7;                                  \
            const uint32_t so = (uint32_t)(rr * ROWB + q * 16);                  \
            const size_t ga = (size_t)(row0 + rr) * K + kel + q * 8;             \
            CP16(sb_ + T_A + so, g_xh + ga);                                     \
        }                                                                        \
        _Pragma("unroll")                                                        \
        for (int t = 0; t < 4; ++t) {                                            \
            const int c_ = tid + (t << 9);                                       \
            const int rr = c_ >> 3, q = c_ & 7;                                  \
            const uint32_t so = (uint32_t)(rr * ROWB + q * 16);                  \
            const size_t gb = (size_t)(col0 + rr) * K + kel + q * 8;             \
            CP16(sb_ + T_B + so, g_wh + gb);                                     \
        }                                                                        \
    } while (0)

    LOAD_STAGE(0, 0);
    CP_COMMIT();
    LOAD_STAGE(1, 1);
    CP_COMMIT();

    int cbuf = 0, lbuf = 2;
    for (int c = 0; c < nchunks; ++c) {
        CP_WAIT1();          // chunk c resident
        __syncthreads();     // all warps past compute(c-1); safe to overwrite lbuf

        if (c + 2 < nchunks) LOAD_STAGE(c + 2, lbuf);
        CP_COMMIT();         // commit every iter keeps group accounting uniform

        const uint32_t sb = sbase + cbuf * STAGE_SZ;
        #pragma unroll
        for (int kk = 0; kk < 4; ++kk) {
            const uint32_t ko = kk << 5;  // 32B per k16 step
            uint32_t ah[4][4];
            #pragma unroll
            for (int mf = 0; mf < 4; ++mf) {
                const uint32_t ao = a_lm + mf * (16 * ROWB) + ko;
                LDSM_X4(ah[mf][0], ah[mf][1], ah[mf][2], ah[mf][3], sb + T_A + ao);
            }
            #pragma unroll
            for (int np = 0; np < 2; ++np) {
                uint32_t bh[4];
                const uint32_t bo = b_lm + np * (16 * ROWB) + ko;
                LDSM_X4(bh[0], bh[1], bh[2], bh[3], sb + T_B + bo);
                #pragma unroll
                for (int mf = 0; mf < 4; ++mf) {
                    MMA_F16(acc[mf][2 * np],     ah[mf], (&bh[0]));
                    MMA_F16(acc[mf][2 * np + 1], ah[mf], (&bh[2]));
                }
            }
        }

        cbuf = (cbuf == NSTAGE - 1) ? 0 : cbuf + 1;
        lbuf = (lbuf == NSTAGE - 1) ? 0 : lbuf + 1;
    }

    // Epilogue: ReLU + store u + global max (operands pre-normalized)
    const int g  = lane >> 2;
    const int tg = lane & 3;
    float tmax = 0.f;
    #pragma unroll
    for (int mf = 0; mf < 4; ++mf) {
        const int ra = row0 + wm * 64 + mf * 16 + g;
        #pragma unroll
        for (int nf = 0; nf < 4; ++nf) {
            const int col = col0 + wn * 32 + nf * 8 + tg * 2;
            float2 v0, v1;
            v0.x = fmaxf(acc[mf][nf][0], 0.f);
            v0.y = fmaxf(acc[mf][nf][1], 0.f);
            v1.x = fmaxf(acc[mf][nf][2], 0.f);
            v1.y = fmaxf(acc[mf][nf][3], 0.f);
            tmax = fmaxf(tmax, fmaxf(fmaxf(v0.x, v0.y), fmaxf(v1.x, v1.y)));
            *reinterpret_cast<float2*>(&g_u[(size_t)ra * N + col])       = v0;
            *reinterpret_cast<float2*>(&g_u[(size_t)(ra + 8) * N + col]) = v1;
        }
    }

    #pragma unroll
    for (int o = 16; o; o >>= 1)
        tmax = fmaxf(tmax, __shfl_xor_sync(0xffffffffu, tmax, o));
    __shared__ float wmax[16];
    if (lane == 0) wmax[wid] = tmax;
    __syncthreads();
    if (tid == 0) {
        float m = wmax[0];
        #pragma unroll
        for (int i = 1; i < 16; ++i) m = fmaxf(m, wmax[i]);
        atomicMax(reinterpret_cast<int*>(&g_gmax), __float_as_int(m));
    }
}

// ---------------------------------------------------------------------------
// Kernel 3: per-row power-law + logprior + row-sum normalize (reg-resident).
// N=2048, 256 threads -> exactly 2 float4 per thread.
// ---------------------------------------------------------------------------
__global__ void __launch_bounds__(256)
finalize_kernel(const float* __restrict__ logprior, const float* __restrict__ lamb_p,
                float* __restrict__ y, int N)
{
    const int r = blockIdx.x;
    const float lamb = lamb_p[0];
    const float inv_umax = 1.f / (g_gmax + EPSV);

    const float4* u4  = reinterpret_cast<const float4*>(&g_u[(size_t)r * N]);
    const float4* lp4 = reinterpret_cast<const float4*>(logprior);

    const int n4 = N >> 2;
    const int nit = n4 / 256;   // 2 for N=2048
    float4 pv[8];
    float s = 0.f;
    #pragma unroll
    for (int j = 0; j < 8; ++j) {
        if (j < nit) {
            const int i = threadIdx.x + j * 256;
            float4 u = u4[i];
            float4 lp = lp4[i];
            float4 p;
            p.x = (u.x > 0.f) ? exp2f(lamb * log2f(u.x * inv_umax)) * expf(lp.x) : 0.f;
            p.y = (u.y > 0.f) ? exp2f(lamb * log2f(u.y * inv_umax)) * expf(lp.y) : 0.f;
            p.z = (u.z > 0.f) ? exp2f(lamb * log2f(u.z * inv_umax)) * expf(lp.z) : 0.f;
            p.w = (u.w > 0.f) ? exp2f(lamb * log2f(u.w * inv_umax)) * expf(lp.w) : 0.f;
            pv[j] = p;
            s += p.x + p.y + p.z + p.w;
        }
    }

    #pragma unroll
    for (int o = 16; o; o >>= 1) s += __shfl_xor_sync(0xffffffffu, s, o);
    __shared__ float red[8];
    __shared__ float inv_sum_sh;
    const int lane = threadIdx.x & 31, wid = threadIdx.x >> 5;
    if (lane == 0) red[wid] = s;
    __syncthreads();
    if (threadIdx.x == 0) {
        float t = 0.f;
        for (int i = 0; i < 8; ++i) t += red[i];
        inv_sum_sh = 1.f / (t + EPSV);
    }
    __syncthreads();
    const float inv_sum = inv_sum_sh;

    float4* y4 = reinterpret_cast<float4*>(y + (size_t)r * N);
    #pragma unroll
    for (int j = 0; j < 8; ++j) {
        if (j < nit) {
            float4 p = pv[j];
            p.x *= inv_sum; p.y *= inv_sum; p.z *= inv_sum; p.w *= inv_sum;
            y4[threadIdx.x + j * 256] = p;
        }
    }
}

// ---------------------------------------------------------------------------
// Launcher. Inputs: x [B,IN] f32, weight [OUT,IN] f32, logprior [OUT] f32,
// lamb [1] f32. Output: y [B,OUT] f32.
// ---------------------------------------------------------------------------
extern "C" void kernel_launch(void* const* d_in, const int* in_sizes, int n_in,
                              void* d_out, int out_size)
{
    const float* x        = (const float*)d_in[0];
    const float* w        = (const float*)d_in[1];
    const float* logprior = (const float*)d_in[2];
    const float* lamb     = (const float*)d_in[3];
    float* y              = (float*)d_out;

    const int OUT = in_sizes[2];
    const int IN  = in_sizes[1] / OUT;
    const int B   = in_sizes[0] / IN;

    cudaFuncSetAttribute(softhebb_mma_gemm,
                         cudaFuncAttributeMaxDynamicSharedMemorySize, DYN_SMEM);

    prep_kernel<<<B + OUT, 256>>>(x, w, B, OUT, IN);

    dim3 grid(OUT / 256, B / 128);
    softhebb_mma_gemm<<<grid, 512, DYN_SMEM>>>(B, OUT, IN);

    finalize_kernel<<<B, 256>>>(logprior, lamb, y, OUT);
}

// round 8
// speedup vs baseline: 6.5600x; 1.0326x over previous
#include <cuda_runtime.h>
#include <cuda_fp16.h>
#include <cstdint>

#define EPSV 1e-9f

// Fixed problem shape: B=16384, IN=K=2048, OUT=2048
#define B_DIM   16384
#define K_DIM   2048
#define O_DIM   2048

// ---------------------------------------------------------------------------
// Device scratch (no allocations allowed in kernel_launch)
// ---------------------------------------------------------------------------
__device__ uint16_t g_u[(size_t)B_DIM * O_DIM];   // relu(cos) scratch, unorm16 (64 MB)
__device__ float g_gmax;
__device__ __align__(16) __half g_xh[(size_t)B_DIM * K_DIM];  // normalized x, fp16
__device__ __align__(16) __half g_wh[(size_t)O_DIM * K_DIM];  // normalized w, fp16

// ---------------------------------------------------------------------------
// PTX helpers (family-safe: ldmatrix, mma.sync, cp.async)
// ---------------------------------------------------------------------------
__device__ __forceinline__ uint32_t smem_u32(const void* p) {
    uint32_t a;
    asm("{ .reg .u64 t; cvta.to.shared.u64 t, %1; cvt.u32.u64 %0, t; }"
        : "=r"(a) : "l"(p));
    return a;
}

#define CP16(saddr, gptr) \
    asm volatile("cp.async.cg.shared.global [%0], [%1], 16;" \
                 :: "r"(saddr), "l"(gptr) : "memory")
#define CP_COMMIT() asm volatile("cp.async.commit_group;" ::: "memory")
#define CP_WAIT1()  asm volatile("cp.async.wait_group 1;" ::: "memory")

#define LDSM_X4(r0, r1, r2, r3, addr) \
    asm volatile("ldmatrix.sync.aligned.m8n8.x4.shared.b16 {%0,%1,%2,%3}, [%4];" \
                 : "=r"(r0), "=r"(r1), "=r"(r2), "=r"(r3) : "r"(addr))

#define MMA_F16(d, a, b) \
    asm volatile("mma.sync.aligned.m16n8k16.row.col.f32.f16.f16.f32 " \
                 "{%0,%1,%2,%3}, {%4,%5,%6,%7}, {%8,%9}, {%0,%1,%2,%3};" \
                 : "+f"((d)[0]), "+f"((d)[1]), "+f"((d)[2]), "+f"((d)[3]) \
                 : "r"((a)[0]), "r"((a)[1]), "r"((a)[2]), "r"((a)[3]),   \
                   "r"((b)[0]), "r"((b)[1]))

// ---------------------------------------------------------------------------
// Kernel 1: per-row L2 normalize -> fp16. Row held in registers.
// Blocks [0,B): x rows -> g_xh; [B,B+OUT): w rows -> g_wh. Resets g_gmax.
// ---------------------------------------------------------------------------
__global__ void __launch_bounds__(256)
prep_kernel(const float* __restrict__ x, const float* __restrict__ w,
            int B, int OUT, int IN)
{
    const int r = blockIdx.x;
    const float* src;
    __half* dst;
    if (r < B) { src = x + (size_t)r * IN;       dst = g_xh + (size_t)r * IN; }
    else       { src = w + (size_t)(r - B) * IN; dst = g_wh + (size_t)(r - B) * IN; }

    const float4* p4 = reinterpret_cast<const float4*>(src);
    float4 v[8];
    const int n4 = IN >> 2;        // 512
    const int nit = n4 / 256;      // 2 for IN=2048

    float s = 0.f;
    #pragma unroll
    for (int j = 0; j < 8; ++j) {
        if (j < nit) {
            v[j] = p4[threadIdx.x + j * 256];
            s += v[j].x * v[j].x + v[j].y * v[j].y + v[j].z * v[j].z + v[j].w * v[j].w;
        }
    }

    #pragma unroll
    for (int o = 16; o; o >>= 1) s += __shfl_xor_sync(0xffffffffu, s, o);
    __shared__ float red[8];
    __shared__ float scale_sh;
    const int lane = threadIdx.x & 31, wid = threadIdx.x >> 5;
    if (lane == 0) red[wid] = s;
    __syncthreads();
    if (threadIdx.x == 0) {
        float t = 0.f;
        for (int i = 0; i < 8; ++i) t += red[i];
        scale_sh = 1.f / (sqrtf(t) + EPSV);
        if (r == 0) g_gmax = 0.f;
    }
    __syncthreads();
    const float sc = scale_sh;

    uint2* d2 = reinterpret_cast<uint2*>(dst);
    #pragma unroll
    for (int j = 0; j < 8; ++j) {
        if (j < nit) {
            __half2 lo = __floats2half2_rn(v[j].x * sc, v[j].y * sc);
            __half2 hi = __floats2half2_rn(v[j].z * sc, v[j].w * sc);
            uint2 u;
            u.x = *reinterpret_cast<uint32_t*>(&lo);
            u.y = *reinterpret_cast<uint32_t*>(&hi);
            d2[threadIdx.x + j * 256] = u;
        }
    }
}

// ---------------------------------------------------------------------------
// Kernel 2: single-term fp16 mma.sync GEMM + fused ReLU/max/unorm16 epilogue.
// CTA 128x256, 512 threads, 16 warps (2 M x 8 N), warp tile 64x32.
// K chunks of 64, cp.async 3-stage pipeline, one __syncthreads per chunk.
// Per kk-step: issue ALL 6 LDSMs, then all 16 MMAs (volatile asm keeps order,
// so this hides LDSM->MMA RAW latency within the warp).
// SMEM per stage: A 128x144B, B 256x144B (128B data + 16B pad).
// ---------------------------------------------------------------------------
#define ROWB     144
#define T_A      0
#define T_B      18432
#define STAGE_SZ 55296
#define NSTAGE   3
#define DYN_SMEM (NSTAGE * STAGE_SZ)

__global__ void __launch_bounds__(512, 1)
softhebb_mma_gemm(int M, int N, int K)
{
    extern __shared__ char sm[];
    const uint32_t sbase = smem_u32(sm);

    const int tid  = threadIdx.x;
    const int wid  = tid >> 5;
    const int lane = tid & 31;
    const int wm   = wid & 1;   // M warp (0..1): rows wm*64..+63
    const int wn   = wid >> 1;  // N warp (0..7): cols wn*32..+31

    const int row0 = blockIdx.y * 128;
    const int col0 = blockIdx.x * 256;

    float acc[4][4][4];   // [mf(m16)][nf(n8)][quad]
    #pragma unroll
    for (int i = 0; i < 4; ++i)
        #pragma unroll
        for (int j = 0; j < 4; ++j)
            #pragma unroll
            for (int q = 0; q < 4; ++q) acc[i][j][q] = 0.f;

    const int nchunks = K >> 6;  // 32

    const uint32_t a_lm = (uint32_t)((wm * 64 + (lane & 15)) * ROWB + (lane >> 4) * 16);
    const uint32_t b_lm = (uint32_t)((wn * 32 + (lane & 7) + ((lane >> 4) << 3)) * ROWB
                                     + (((lane >> 3) & 1) << 4));

    // Per-stage load, 512 threads: A 1024 x 16B chunks (2/thread),
    // B 2048 chunks (4/thread) -> 6 CP16 per thread.
    #define LOAD_STAGE(chunk, stg) do {                                          \
        const int kel = (chunk) << 6;                                            \
        const uint32_t sb_ = sbase + (stg) * STAGE_SZ;                           \
        _Pragma("unroll")                                                        \
        for (int t = 0; t < 2; ++t) {                                            \
            const int c_ = tid + (t << 9);                                       \
            const int rr = c_ >> 3, q = c_ & 7;                                  \
            const uint32_t so = (uint32_t)(rr * ROWB + q * 16);                  \
            const size_t ga = (size_t)(row0 + rr) * K + kel + q * 8;             \
            CP16(sb_ + T_A + so, g_xh + ga);                                     \
        }                                                                        \
        _Pragma("unroll")                                                        \
        for (int t = 0; t < 4; ++t) {                                            \
            const int c_ = tid + (t << 9);                                       \
            const int rr = c_ >> 3, q = c_ & 7;                                  \
            const uint32_t so = (uint32_t)(rr * ROWB + q * 16);                  \
            const size_t gb = (size_t)(col0 + rr) * K + kel + q * 8;             \
            CP16(sb_ + T_B + so, g_wh + gb);                                     \
        }                                                                        \
    } while (0)

    LOAD_STAGE(0, 0);
    CP_COMMIT();
    LOAD_STAGE(1, 1);
    CP_COMMIT();

    int cbuf = 0, lbuf = 2;
    for (int c = 0; c < nchunks; ++c) {
        CP_WAIT1();          // chunk c resident
        __syncthreads();     // all warps past compute(c-1); safe to overwrite lbuf

        if (c + 2 < nchunks) LOAD_STAGE(c + 2, lbuf);
        CP_COMMIT();         // commit every iter keeps group accounting uniform

        const uint32_t sb = sbase + cbuf * STAGE_SZ;
        #pragma unroll
        for (int kk = 0; kk < 4; ++kk) {
            const uint32_t ko = kk << 5;  // 32B per k16 step
            uint32_t ah[4][4];
            uint32_t bh[2][4];
            // --- all fragment loads first ---
            #pragma unroll
            for (int mf = 0; mf < 4; ++mf) {
                const uint32_t ao = a_lm + mf * (16 * ROWB) + ko;
                LDSM_X4(ah[mf][0], ah[mf][1], ah[mf][2], ah[mf][3], sb + T_A + ao);
            }
            #pragma unroll
            for (int np = 0; np < 2; ++np) {
                const uint32_t bo = b_lm + np * (16 * ROWB) + ko;
                LDSM_X4(bh[np][0], bh[np][1], bh[np][2], bh[np][3], sb + T_B + bo);
            }
            // --- then all MMAs ---
            #pragma unroll
            for (int np = 0; np < 2; ++np) {
                #pragma unroll
                for (int mf = 0; mf < 4; ++mf) {
                    MMA_F16(acc[mf][2 * np],     ah[mf], (&bh[np][0]));
                    MMA_F16(acc[mf][2 * np + 1], ah[mf], (&bh[np][2]));
                }
            }
        }

        cbuf = (cbuf == NSTAGE - 1) ? 0 : cbuf + 1;
        lbuf = (lbuf == NSTAGE - 1) ? 0 : lbuf + 1;
    }

    // Epilogue: ReLU + clamp + unorm16 store + global max
    const int g  = lane >> 2;
    const int tg = lane & 3;
    float tmax = 0.f;
    #pragma unroll
    for (int mf = 0; mf < 4; ++mf) {
        const int ra = row0 + wm * 64 + mf * 16 + g;
        #pragma unroll
        for (int nf = 0; nf < 4; ++nf) {
            const int col = col0 + wn * 32 + nf * 8 + tg * 2;
            float a0 = fminf(fmaxf(acc[mf][nf][0], 0.f), 1.f);
            float a1 = fminf(fmaxf(acc[mf][nf][1], 0.f), 1.f);
            float b0 = fminf(fmaxf(acc[mf][nf][2], 0.f), 1.f);
            float b1 = fminf(fmaxf(acc[mf][nf][3], 0.f), 1.f);
            tmax = fmaxf(tmax, fmaxf(fmaxf(a0, a1), fmaxf(b0, b1)));
            const uint32_t p0 = __float2uint_rn(a0 * 65535.f) |
                                (__float2uint_rn(a1 * 65535.f) << 16);
            const uint32_t p1 = __float2uint_rn(b0 * 65535.f) |
                                (__float2uint_rn(b1 * 65535.f) << 16);
            *reinterpret_cast<uint32_t*>(&g_u[(size_t)ra * N + col])       = p0;
            *reinterpret_cast<uint32_t*>(&g_u[(size_t)(ra + 8) * N + col]) = p1;
        }
    }

    #pragma unroll
    for (int o = 16; o; o >>= 1)
        tmax = fmaxf(tmax, __shfl_xor_sync(0xffffffffu, tmax, o));
    __shared__ float wmax[16];
    if (lane == 0) wmax[wid] = tmax;
    __syncthreads();
    if (tid == 0) {
        float m = wmax[0];
        #pragma unroll
        for (int i = 1; i < 16; ++i) m = fmaxf(m, wmax[i]);
        atomicMax(reinterpret_cast<int*>(&g_gmax), __float_as_int(m));
    }
}

// ---------------------------------------------------------------------------
// Kernel 3: per-row power-law + logprior + row-sum normalize.
// Reads unorm16 u (uint4 = 8 values per thread), reg-resident.
// ---------------------------------------------------------------------------
__global__ void __launch_bounds__(256)
finalize_kernel(const float* __restrict__ logprior, const float* __restrict__ lamb_p,
                float* __restrict__ y, int N)
{
    const int r = blockIdx.x;
    const float lamb = lamb_p[0];
    const float inv_umax = 1.f / (g_gmax + EPSV);
    const float dq = 1.f / 65535.f;

    const int i = threadIdx.x;   // 256 threads, 8 u values each (N=2048)
    const uint4 q = reinterpret_cast<const uint4*>(g_u + (size_t)r * N)[i];
    const float4 lp0 = reinterpret_cast<const float4*>(logprior)[2 * i];
    const float4 lp1 = reinterpret_cast<const float4*>(logprior)[2 * i + 1];

    float u[8];
    u[0] = (float)(q.x & 0xffff) * dq; u[1] = (float)(q.x >> 16) * dq;
    u[2] = (float)(q.y & 0xffff) * dq; u[3] = (float)(q.y >> 16) * dq;
    u[4] = (float)(q.z & 0xffff) * dq; u[5] = (float)(q.z >> 16) * dq;
    u[6] = (float)(q.w & 0xffff) * dq; u[7] = (float)(q.w >> 16) * dq;
    const float lp[8] = {lp0.x, lp0.y, lp0.z, lp0.w, lp1.x, lp1.y, lp1.z, lp1.w};

    float p[8];
    float s = 0.f;
    #pragma unroll
    for (int j = 0; j < 8; ++j) {
        p[j] = (u[j] > 0.f)
             ? exp2f(lamb * log2f(u[j] * inv_umax)) * expf(lp[j]) : 0.f;
        s += p[j];
    }

    #pragma unroll
    for (int o = 16; o; o >>= 1) s += __shfl_xor_sync(0xffffffffu, s, o);
    __shared__ float red[8];
    __shared__ float inv_sum_sh;
    const int lane = threadIdx.x & 31, wid = threadIdx.x >> 5;
    if (lane == 0) red[wid] = s;
    __syncthreads();
    if (threadIdx.x == 0) {
        float t = 0.f;
        for (int k = 0; k < 8; ++k) t += red[k];
        inv_sum_sh = 1.f / (t + EPSV);
    }
    __syncthreads();
    const float inv_sum = inv_sum_sh;

    float4* y4 = reinterpret_cast<float4*>(y + (size_t)r * N);
    float4 o0, o1;
    o0.x = p[0] * inv_sum; o0.y = p[1] * inv_sum;
    o0.z = p[2] * inv_sum; o0.w = p[3] * inv_sum;
    o1.x = p[4] * inv_sum; o1.y = p[5] * inv_sum;
    o1.z = p[6] * inv_sum; o1.w = p[7] * inv_sum;
    y4[2 * i]     = o0;
    y4[2 * i + 1] = o1;
}

// ---------------------------------------------------------------------------
// Launcher. Inputs: x [B,IN] f32, weight [OUT,IN] f32, logprior [OUT] f32,
// lamb [1] f32. Output: y [B,OUT] f32.
// ---------------------------------------------------------------------------
extern "C" void kernel_launch(void* const* d_in, const int* in_sizes, int n_in,
                              void* d_out, int out_size)
{
    const float* x        = (const float*)d_in[0];
    const float* w        = (const float*)d_in[1];
    const float* logprior = (const float*)d_in[2];
    const float* lamb     = (const float*)d_in[3];
    float* y              = (float*)d_out;

    const int OUT = in_sizes[2];
    const int IN  = in_sizes[1] / OUT;
    const int B   = in_sizes[0] / IN;

    cudaFuncSetAttribute(softhebb_mma_gemm,
                         cudaFuncAttributeMaxDynamicSharedMemorySize, DYN_SMEM);

    prep_kernel<<<B + OUT, 256>>>(x, w, B, OUT, IN);

    dim3 grid(OUT / 256, B / 128);
    softhebb_mma_gemm<<<grid, 512, DYN_SMEM>>>(B, OUT, IN);

    finalize_kernel<<<B, 256>>>(logprior, lamb, y, OUT);
}

// round 9
// speedup vs baseline: 6.6921x; 1.0201x over previous
#include <cuda_runtime.h>
#include <cuda_fp16.h>
#include <cstdint>

#define EPSV 1e-9f

// Fixed problem shape: B=16384, IN=K=2048, OUT=2048
#define B_DIM   16384
#define K_DIM   2048
#define O_DIM   2048

// ---------------------------------------------------------------------------
// Device scratch (no allocations allowed in kernel_launch)
// ---------------------------------------------------------------------------
__device__ uint16_t g_u[(size_t)B_DIM * O_DIM];   // relu(cos) scratch, unorm16 (64 MB)
__device__ float g_gmax;
__device__ __align__(16) __half g_xh[(size_t)B_DIM * K_DIM];  // normalized x, fp16
__device__ __align__(16) __half g_wh[(size_t)O_DIM * K_DIM];  // normalized w, fp16

// ---------------------------------------------------------------------------
// PTX helpers (family-safe: ldmatrix, mma.sync, cp.async)
// ---------------------------------------------------------------------------
__device__ __forceinline__ uint32_t smem_u32(const void* p) {
    uint32_t a;
    asm("{ .reg .u64 t; cvta.to.shared.u64 t, %1; cvt.u32.u64 %0, t; }"
        : "=r"(a) : "l"(p));
    return a;
}

#define CP16(saddr, gptr) \
    asm volatile("cp.async.cg.shared.global [%0], [%1], 16;" \
                 :: "r"(saddr), "l"(gptr) : "memory")
#define CP_COMMIT() asm volatile("cp.async.commit_group;" ::: "memory")
#define CP_WAIT1()  asm volatile("cp.async.wait_group 1;" ::: "memory")

#define LDSM_X4(r0, r1, r2, r3, addr) \
    asm volatile("ldmatrix.sync.aligned.m8n8.x4.shared.b16 {%0,%1,%2,%3}, [%4];" \
                 : "=r"(r0), "=r"(r1), "=r"(r2), "=r"(r3) : "r"(addr))

#define MMA_F16(d, a, b) \
    asm volatile("mma.sync.aligned.m16n8k16.row.col.f32.f16.f16.f32 " \
                 "{%0,%1,%2,%3}, {%4,%5,%6,%7}, {%8,%9}, {%0,%1,%2,%3};" \
                 : "+f"((d)[0]), "+f"((d)[1]), "+f"((d)[2]), "+f"((d)[3]) \
                 : "r"((a)[0]), "r"((a)[1]), "r"((a)[2]), "r"((a)[3]),   \
                   "r"((b)[0]), "r"((b)[1]))

// ---------------------------------------------------------------------------
// Kernel 1: per-row L2 normalize -> fp16. WARP-PER-ROW: 32 lanes hold the
// whole 2048-elem row in registers (16 float4 each); shfl-only reduction,
// no smem, no __syncthreads. 8 rows per 256-thread block.
// Rows [0,B): x -> g_xh; [B,B+OUT): w -> g_wh. Block 0 resets g_gmax.
// ---------------------------------------------------------------------------
__global__ void __launch_bounds__(256)
prep_kernel(const float* __restrict__ x, const float* __restrict__ w,
            int B, int OUT, int IN)
{
    const int warp = threadIdx.x >> 5;
    const int lane = threadIdx.x & 31;
    const int r = blockIdx.x * 8 + warp;

    if (blockIdx.x == 0 && threadIdx.x == 0) g_gmax = 0.f;
    if (r >= B + OUT) return;

    const float* src;
    __half* dst;
    if (r < B) { src = x + (size_t)r * IN;       dst = g_xh + (size_t)r * IN; }
    else       { src = w + (size_t)(r - B) * IN; dst = g_wh + (size_t)(r - B) * IN; }

    // 2048 elems / 32 lanes = 64 elems = 16 float4 per lane
    const float4* p4 = reinterpret_cast<const float4*>(src);
    float4 v[16];
    #pragma unroll
    for (int j = 0; j < 16; ++j) v[j] = p4[lane + j * 32];

    float s = 0.f;
    #pragma unroll
    for (int j = 0; j < 16; ++j)
        s += v[j].x * v[j].x + v[j].y * v[j].y + v[j].z * v[j].z + v[j].w * v[j].w;

    #pragma unroll
    for (int o = 16; o; o >>= 1) s += __shfl_xor_sync(0xffffffffu, s, o);
    const float sc = 1.f / (sqrtf(s) + EPSV);

    uint2* d2 = reinterpret_cast<uint2*>(dst);
    #pragma unroll
    for (int j = 0; j < 16; ++j) {
        __half2 lo = __floats2half2_rn(v[j].x * sc, v[j].y * sc);
        __half2 hi = __floats2half2_rn(v[j].z * sc, v[j].w * sc);
        uint2 u;
        u.x = *reinterpret_cast<uint32_t*>(&lo);
        u.y = *reinterpret_cast<uint32_t*>(&hi);
        d2[lane + j * 32] = u;
    }
}

// ---------------------------------------------------------------------------
// Kernel 2: single-term fp16 mma.sync GEMM + fused ReLU/max/unorm16 epilogue.
// CTA 128x256, 512 threads, 16 warps (2 M x 8 N), warp tile 64x32.
// K chunks of 64, cp.async 3-stage pipeline, one __syncthreads per chunk.
// (Empirically at the legacy-HMMA roofline: ~14.8 cyc/MMA/SMSP.)
// ---------------------------------------------------------------------------
#define ROWB     144
#define T_A      0
#define T_B      18432
#define STAGE_SZ 55296
#define NSTAGE   3
#define DYN_SMEM (NSTAGE * STAGE_SZ)

__global__ void __launch_bounds__(512, 1)
softhebb_mma_gemm(int M, int N, int K)
{
    extern __shared__ char sm[];
    const uint32_t sbase = smem_u32(sm);

    const int tid  = threadIdx.x;
    const int wid  = tid >> 5;
    const int lane = tid & 31;
    const int wm   = wid & 1;   // M warp (0..1): rows wm*64..+63
    const int wn   = wid >> 1;  // N warp (0..7): cols wn*32..+31

    const int row0 = blockIdx.y * 128;
    const int col0 = blockIdx.x * 256;

    float acc[4][4][4];   // [mf(m16)][nf(n8)][quad]
    #pragma unroll
    for (int i = 0; i < 4; ++i)
        #pragma unroll
        for (int j = 0; j < 4; ++j)
            #pragma unroll
            for (int q = 0; q < 4; ++q) acc[i][j][q] = 0.f;

    const int nchunks = K >> 6;  // 32

    const uint32_t a_lm = (uint32_t)((wm * 64 + (lane & 15)) * ROWB + (lane >> 4) * 16);
    const uint32_t b_lm = (uint32_t)((wn * 32 + (lane & 7) + ((lane >> 4) << 3)) * ROWB
                                     + (((lane >> 3) & 1) << 4));

    #define LOAD_STAGE(chunk, stg) do {                                          \
        const int kel = (chunk) << 6;                                            \
        const uint32_t sb_ = sbase + (stg) * STAGE_SZ;                           \
        _Pragma("unroll")                                                        \
        for (int t = 0; t < 2; ++t) {                                            \
            const int c_ = tid + (t << 9);                                       \
            const int rr = c_ >> 3, q = c_ & 7;                                  \
            const uint32_t so = (uint32_t)(rr * ROWB + q * 16);                  \
            const size_t ga = (size_t)(row0 + rr) * K + kel + q * 8;             \
            CP16(sb_ + T_A + so, g_xh + ga);                                     \
        }                                                                        \
        _Pragma("unroll")                                                        \
        for (int t = 0; t < 4; ++t) {                                            \
            const int c_ = tid + (t << 9);                                       \
            const int rr = c_ >> 3, q = c_ & 7;                                  \
            const uint32_t so = (uint32_t)(rr * ROWB + q * 16);                  \
            const size_t gb = (size_t)(col0 + rr) * K + kel + q * 8;             \
            CP16(sb_ + T_B + so, g_wh + gb);                                     \
        }                                                                        \
    } while (0)

    LOAD_STAGE(0, 0);
    CP_COMMIT();
    LOAD_STAGE(1, 1);
    CP_COMMIT();

    int cbuf = 0, lbuf = 2;
    for (int c = 0; c < nchunks; ++c) {
        CP_WAIT1();
        __syncthreads();

        if (c + 2 < nchunks) LOAD_STAGE(c + 2, lbuf);
        CP_COMMIT();

        const uint32_t sb = sbase + cbuf * STAGE_SZ;
        #pragma unroll
        for (int kk = 0; kk < 4; ++kk) {
            const uint32_t ko = kk << 5;
            uint32_t ah[4][4];
            uint32_t bh[2][4];
            #pragma unroll
            for (int mf = 0; mf < 4; ++mf) {
                const uint32_t ao = a_lm + mf * (16 * ROWB) + ko;
                LDSM_X4(ah[mf][0], ah[mf][1], ah[mf][2], ah[mf][3], sb + T_A + ao);
            }
            #pragma unroll
            for (int np = 0; np < 2; ++np) {
                const uint32_t bo = b_lm + np * (16 * ROWB) + ko;
                LDSM_X4(bh[np][0], bh[np][1], bh[np][2], bh[np][3], sb + T_B + bo);
            }
            #pragma unroll
            for (int np = 0; np < 2; ++np) {
                #pragma unroll
                for (int mf = 0; mf < 4; ++mf) {
                    MMA_F16(acc[mf][2 * np],     ah[mf], (&bh[np][0]));
                    MMA_F16(acc[mf][2 * np + 1], ah[mf], (&bh[np][2]));
                }
            }
        }

        cbuf = (cbuf == NSTAGE - 1) ? 0 : cbuf + 1;
        lbuf = (lbuf == NSTAGE - 1) ? 0 : lbuf + 1;
    }

    // Epilogue: ReLU + clamp + unorm16 store + global max
    const int g  = lane >> 2;
    const int tg = lane & 3;
    float tmax = 0.f;
    #pragma unroll
    for (int mf = 0; mf < 4; ++mf) {
        const int ra = row0 + wm * 64 + mf * 16 + g;
        #pragma unroll
        for (int nf = 0; nf < 4; ++nf) {
            const int col = col0 + wn * 32 + nf * 8 + tg * 2;
            float a0 = fminf(fmaxf(acc[mf][nf][0], 0.f), 1.f);
            float a1 = fminf(fmaxf(acc[mf][nf][1], 0.f), 1.f);
            float b0 = fminf(fmaxf(acc[mf][nf][2], 0.f), 1.f);
            float b1 = fminf(fmaxf(acc[mf][nf][3], 0.f), 1.f);
            tmax = fmaxf(tmax, fmaxf(fmaxf(a0, a1), fmaxf(b0, b1)));
            const uint32_t p0 = __float2uint_rn(a0 * 65535.f) |
                                (__float2uint_rn(a1 * 65535.f) << 16);
            const uint32_t p1 = __float2uint_rn(b0 * 65535.f) |
                                (__float2uint_rn(b1 * 65535.f) << 16);
            *reinterpret_cast<uint32_t*>(&g_u[(size_t)ra * N + col])       = p0;
            *reinterpret_cast<uint32_t*>(&g_u[(size_t)(ra + 8) * N + col]) = p1;
        }
    }

    #pragma unroll
    for (int o = 16; o; o >>= 1)
        tmax = fmaxf(tmax, __shfl_xor_sync(0xffffffffu, tmax, o));
    __shared__ float wmax[16];
    if (lane == 0) wmax[wid] = tmax;
    __syncthreads();
    if (tid == 0) {
        float m = wmax[0];
        #pragma unroll
        for (int i = 1; i < 16; ++i) m = fmaxf(m, wmax[i]);
        atomicMax(reinterpret_cast<int*>(&g_gmax), __float_as_int(m));
    }
}

// ---------------------------------------------------------------------------
// Kernel 3: per-row power-law + logprior + row-sum normalize.
// Reads unorm16 u (uint4 = 8 values per thread), reg-resident.
// ---------------------------------------------------------------------------
__global__ void __launch_bounds__(256)
finalize_kernel(const float* __restrict__ logprior, const float* __restrict__ lamb_p,
                float* __restrict__ y, int N)
{
    const int r = blockIdx.x;
    const float lamb = lamb_p[0];
    const float inv_umax = 1.f / (g_gmax + EPSV);
    const float dq = 1.f / 65535.f;

    const int i = threadIdx.x;   // 256 threads, 8 u values each (N=2048)
    const uint4 q = reinterpret_cast<const uint4*>(g_u + (size_t)r * N)[i];
    const float4 lp0 = reinterpret_cast<const float4*>(logprior)[2 * i];
    const float4 lp1 = reinterpret_cast<const float4*>(logprior)[2 * i + 1];

    float u[8];
    u[0] = (float)(q.x & 0xffff) * dq; u[1] = (float)(q.x >> 16) * dq;
    u[2] = (float)(q.y & 0xffff) * dq; u[3] = (float)(q.y >> 16) * dq;
    u[4] = (float)(q.z & 0xffff) * dq; u[5] = (float)(q.z >> 16) * dq;
    u[6] = (float)(q.w & 0xffff) * dq; u[7] = (float)(q.w >> 16) * dq;
    const float lp[8] = {lp0.x, lp0.y, lp0.z, lp0.w, lp1.x, lp1.y, lp1.z, lp1.w};

    float p[8];
    float s = 0.f;
    #pragma unroll
    for (int j = 0; j < 8; ++j) {
        p[j] = (u[j] > 0.f)
             ? exp2f(lamb * log2f(u[j] * inv_umax)) * expf(lp[j]) : 0.f;
        s += p[j];
    }

    #pragma unroll
    for (int o = 16; o; o >>= 1) s += __shfl_xor_sync(0xffffffffu, s, o);
    __shared__ float red[8];
    __shared__ float inv_sum_sh;
    const int lane = threadIdx.x & 31, wid = threadIdx.x >> 5;
    if (lane == 0) red[wid] = s;
    __syncthreads();
    if (threadIdx.x == 0) {
        float t = 0.f;
        for (int k = 0; k < 8; ++k) t += red[k];
        inv_sum_sh = 1.f / (t + EPSV);
    }
    __syncthreads();
    const float inv_sum = inv_sum_sh;

    float4* y4 = reinterpret_cast<float4*>(y + (size_t)r * N);
    float4 o0, o1;
    o0.x = p[0] * inv_sum; o0.y = p[1] * inv_sum;
    o0.z = p[2] * inv_sum; o0.w = p[3] * inv_sum;
    o1.x = p[4] * inv_sum; o1.y = p[5] * inv_sum;
    o1.z = p[6] * inv_sum; o1.w = p[7] * inv_sum;
    y4[2 * i]     = o0;
    y4[2 * i + 1] = o1;
}

// ---------------------------------------------------------------------------
// Launcher. Inputs: x [B,IN] f32, weight [OUT,IN] f32, logprior [OUT] f32,
// lamb [1] f32. Output: y [B,OUT] f32.
// ---------------------------------------------------------------------------
extern "C" void kernel_launch(void* const* d_in, const int* in_sizes, int n_in,
                              void* d_out, int out_size)
{
    const float* x        = (const float*)d_in[0];
    const float* w        = (const float*)d_in[1];
    const float* logprior = (const float*)d_in[2];
    const float* lamb     = (const float*)d_in[3];
    float* y              = (float*)d_out;

    const int OUT = in_sizes[2];
    const int IN  = in_sizes[1] / OUT;
    const int B   = in_sizes[0] / IN;

    cudaFuncSetAttribute(softhebb_mma_gemm,
                         cudaFuncAttributeMaxDynamicSharedMemorySize, DYN_SMEM);

    prep_kernel<<<(B + OUT + 7) / 8, 256>>>(x, w, B, OUT, IN);

    dim3 grid(OUT / 256, B / 128);
    softhebb_mma_gemm<<<grid, 512, DYN_SMEM>>>(B, OUT, IN);

    finalize_kernel<<<B, 256>>>(logprior, lamb, y, OUT);
}